// round 2
// baseline (speedup 1.0000x reference)
#include <cuda_runtime.h>
#include <cstddef>

#define NT 512
#define BB 8

// smem layout in floats
#define OFF_XS   0        // [8][30][25]  = 6000
#define OFF_H1   6000     // [8][21][100] = 16800
#define OFF_Y    22800    // [8][9][100]  = 7200
#define OFF_H11  30000    // [8][5][201]  = 8040
#define OFF_FEAT 38040    // [8][200]     = 1600
#define OFF_HF   39640    // [8][100]     = 800
#define OFF_W    40440    // weight chunk buffer, 16000 floats
#define SMEM_FLOATS 56440 // 225760 bytes

__global__ __launch_bounds__(NT, 1) void mga_kernel(
    const float* __restrict__ x, const int* __restrict__ task_labels,
    const float* __restrict__ w1_0, const float* __restrict__ b1_0,
    const float* __restrict__ w2_0, const float* __restrict__ b2_0,
    const float* __restrict__ wd_0, const float* __restrict__ bd_0,
    const float* __restrict__ w1_1, const float* __restrict__ b1_1,
    const float* __restrict__ w2_1, const float* __restrict__ b2_1,
    const float* __restrict__ wd_1, const float* __restrict__ bd_1,
    const float* __restrict__ hw1, const float* __restrict__ hb1,
    const float* __restrict__ hw2, const float* __restrict__ hb2,
    float* __restrict__ out)
{
    extern __shared__ float sm[];
    const int tid = threadIdx.x;
    const int b0  = blockIdx.x * BB;

    // ---------------- load x slice (t in [231,255]) and w1_0 (fits whole) ----------------
    for (int i = tid; i < 6000; i += NT) {
        int bb = i / 750; int r = i - bb * 750; int ci = r / 25; int xt = r - ci * 25;
        sm[OFF_XS + i] = x[((size_t)(b0 + bb) * 30 + ci) * 256 + 231 + xt];
    }
    for (int i = tid; i < 15000; i += NT) sm[OFF_W + i] = w1_0[i];
    __syncthreads();

    // ---------------- stage 1: h1_0 = relu(conv1) at 21 pts, dil=1 ----------------
    for (int task = tid; task < 800; task += NT) {
        int co = task >> 3, bb = task & 7;
        float acc[21];
        float bias = __ldg(b1_0 + co);
        #pragma unroll
        for (int t = 0; t < 21; t++) acc[t] = bias;
        const float* wr = &sm[OFF_W + co * 150];
        const float* xb = &sm[OFF_XS + bb * 750];
        for (int ci = 0; ci < 30; ci++) {
            float xw[25];
            #pragma unroll
            for (int t = 0; t < 25; t++) xw[t] = xb[ci * 25 + t];
            #pragma unroll
            for (int k = 0; k < 5; k++) {
                float w = wr[ci * 5 + k];
                #pragma unroll
                for (int t = 0; t < 21; t++) acc[t] = fmaf(xw[t + k], w, acc[t]);
            }
        }
        float* hb = &sm[OFF_H1 + bb * 2100 + co];
        #pragma unroll
        for (int t = 0; t < 21; t++) hb[t * 100] = fmaxf(acc[t], 0.f);
    }

    // ---------------- stage 2: y = relu(relu(conv2(h1)) + res) at 9 pts ----------------
    {
        const int pid = tid;                 // pid<400 active, pair (co, co+50)
        const int co = pid >> 3, bb = pid & 7;
        float a0[9], a1[9];
        if (pid < 400) {
            float bi0 = __ldg(b2_0 + co), bi1 = __ldg(b2_0 + co + 50);
            #pragma unroll
            for (int j = 0; j < 9; j++) { a0[j] = bi0; a1[j] = bi1; }
        }
        for (int ci0 = 0; ci0 < 100; ci0 += 32) {
            int C = (100 - ci0) < 32 ? (100 - ci0) : 32;
            __syncthreads();
            int n = 100 * C * 5;
            for (int i = tid; i < n; i += NT) {
                int cco = i / (C * 5); int r = i - cco * (C * 5);
                sm[OFF_W + i] = w2_0[cco * 500 + ci0 * 5 + r];
            }
            __syncthreads();
            if (pid < 400) {
                for (int cc = 0; cc < C; cc++) {
                    float hv[21];
                    const float* hp = &sm[OFF_H1 + bb * 2100 + ci0 + cc];
                    #pragma unroll
                    for (int t = 0; t < 21; t++) hv[t] = hp[t * 100];
                    const float* w0 = &sm[OFF_W + (co)      * (C * 5) + cc * 5];
                    const float* w1 = &sm[OFF_W + (co + 50) * (C * 5) + cc * 5];
                    #pragma unroll
                    for (int k = 0; k < 5; k++) {
                        float wa = w0[k], wb = w1[k];
                        #pragma unroll
                        for (int j = 0; j < 9; j++) {
                            a0[j] = fmaf(hv[2 * j + k], wa, a0[j]);
                            a1[j] = fmaf(hv[2 * j + k], wb, a1[j]);
                        }
                    }
                }
            }
        }
        if (pid < 400) {
            // inner relu on conv2 output (h = relu(conv2(...)))
            #pragma unroll
            for (int j = 0; j < 9; j++) { a0[j] = fmaxf(a0[j], 0.f); a1[j] = fmaxf(a1[j], 0.f); }
            // residual: bd + sum_ci xs[bb][ci][8+2j] * wd_0[co][ci]
            float rb0 = __ldg(bd_0 + co), rb1 = __ldg(bd_0 + co + 50);
            #pragma unroll
            for (int j = 0; j < 9; j++) { a0[j] += rb0; a1[j] += rb1; }
            for (int ci = 0; ci < 30; ci++) {
                float wv0 = __ldg(wd_0 + co * 30 + ci);
                float wv1 = __ldg(wd_0 + (co + 50) * 30 + ci);
                const float* xb = &sm[OFF_XS + bb * 750 + ci * 25 + 8];
                #pragma unroll
                for (int j = 0; j < 9; j++) {
                    float xv = xb[2 * j];
                    a0[j] = fmaf(xv, wv0, a0[j]);
                    a1[j] = fmaf(xv, wv1, a1[j]);
                }
            }
            float* yb = &sm[OFF_Y + bb * 900];
            #pragma unroll
            for (int j = 0; j < 9; j++) {
                yb[j * 100 + co]      = fmaxf(a0[j], 0.f);
                yb[j * 100 + co + 50] = fmaxf(a1[j], 0.f);
            }
        }
    }

    // ---------------- stage 3: h1_1 = relu(conv1(y)) at 5 pts, dil=2 ----------------
    {
        float a[2][2][5];
        #pragma unroll
        for (int s = 0; s < 2; s++) {
            int t = tid + s * NT;
            if (t < 800) {
                int co2 = t >> 3;
                float bi0 = __ldg(b1_1 + co2), bi1 = __ldg(b1_1 + co2 + 100);
                #pragma unroll
                for (int i = 0; i < 5; i++) { a[s][0][i] = bi0; a[s][1][i] = bi1; }
            }
        }
        for (int ci0 = 0; ci0 < 100; ci0 += 16) {
            int C = (100 - ci0) < 16 ? (100 - ci0) : 16;
            __syncthreads();
            int n = 200 * C * 5;
            for (int i = tid; i < n; i += NT) {
                int cco = i / (C * 5); int r = i - cco * (C * 5);
                sm[OFF_W + i] = w1_1[cco * 500 + ci0 * 5 + r];
            }
            __syncthreads();
            #pragma unroll
            for (int s = 0; s < 2; s++) {
                int t = tid + s * NT;
                if (t < 800) {
                    int co2 = t >> 3, bb = t & 7;
                    for (int cc = 0; cc < C; cc++) {
                        float yv[9];
                        const float* yp = &sm[OFF_Y + bb * 900 + ci0 + cc];
                        #pragma unroll
                        for (int j = 0; j < 9; j++) yv[j] = yp[j * 100];
                        const float* wA = &sm[OFF_W + (co2)       * (C * 5) + cc * 5];
                        const float* wB = &sm[OFF_W + (co2 + 100) * (C * 5) + cc * 5];
                        #pragma unroll
                        for (int k = 0; k < 5; k++) {
                            float wa = wA[k], wb = wB[k];
                            #pragma unroll
                            for (int i = 0; i < 5; i++) {
                                a[s][0][i] = fmaf(yv[i + k], wa, a[s][0][i]);
                                a[s][1][i] = fmaf(yv[i + k], wb, a[s][1][i]);
                            }
                        }
                    }
                }
            }
        }
        #pragma unroll
        for (int s = 0; s < 2; s++) {
            int t = tid + s * NT;
            if (t < 800) {
                int co2 = t >> 3, bb = t & 7;
                float* hp = &sm[OFF_H11 + bb * 1005];
                #pragma unroll
                for (int i = 0; i < 5; i++) {
                    hp[i * 201 + co2]       = fmaxf(a[s][0][i], 0.f);
                    hp[i * 201 + co2 + 100] = fmaxf(a[s][1][i], 0.f);
                }
            }
        }
    }

    // ---------------- stage 4: feat = relu(relu(conv2_1) + res1) at t=255, dil=2 ----------------
    {
        const int pid = tid;                   // pid<200: 4 co2 x 2 bb per thread
        const int cg = pid >> 2, bbg = pid & 3;
        float a[4][2];
        if (pid < 200) {
            #pragma unroll
            for (int r = 0; r < 4; r++) {
                float bi = __ldg(b2_1 + cg + 50 * r);
                a[r][0] = bi; a[r][1] = bi;
            }
        }
        for (int ci0 = 0; ci0 < 200; ci0 += 16) {
            int C = (200 - ci0) < 16 ? (200 - ci0) : 16;
            __syncthreads();
            int n = 200 * C * 5;
            for (int i = tid; i < n; i += NT) {
                int cco = i / (C * 5); int r = i - cco * (C * 5);
                sm[OFF_W + i] = w2_1[cco * 1000 + ci0 * 5 + r];
            }
            __syncthreads();
            if (pid < 200) {
                for (int cc = 0; cc < C; cc++) {
                    float h0[5], h1v[5];
                    const float* p0 = &sm[OFF_H11 + (2 * bbg) * 1005 + ci0 + cc];
                    const float* p1 = p0 + 1005;
                    #pragma unroll
                    for (int k = 0; k < 5; k++) { h0[k] = p0[k * 201]; h1v[k] = p1[k * 201]; }
                    #pragma unroll
                    for (int r = 0; r < 4; r++) {
                        const float* wp = &sm[OFF_W + (cg + 50 * r) * (C * 5) + cc * 5];
                        #pragma unroll
                        for (int k = 0; k < 5; k++) {
                            float w = wp[k];
                            a[r][0] = fmaf(h0[k],  w, a[r][0]);
                            a[r][1] = fmaf(h1v[k], w, a[r][1]);
                        }
                    }
                }
            }
        }
        if (pid < 200) {
            const float* y0 = &sm[OFF_Y + (2 * bbg)     * 900 + 800];  // y[bb][8][*] (t=255)
            const float* y1 = &sm[OFF_Y + (2 * bbg + 1) * 900 + 800];
            #pragma unroll
            for (int r = 0; r < 4; r++) {
                int co2 = cg + 50 * r;
                float r0 = __ldg(bd_1 + co2), r1 = r0;
                for (int ci = 0; ci < 100; ci++) {
                    float wv = __ldg(wd_1 + co2 * 100 + ci);
                    r0 = fmaf(y0[ci], wv, r0);
                    r1 = fmaf(y1[ci], wv, r1);
                }
                // inner relu on conv2 output, then add residual, then outer relu
                sm[OFF_FEAT + (2 * bbg)     * 200 + co2] = fmaxf(fmaxf(a[r][0], 0.f) + r0, 0.f);
                sm[OFF_FEAT + (2 * bbg + 1) * 200 + co2] = fmaxf(fmaxf(a[r][1], 0.f) + r1, 0.f);
            }
        }
    }
    __syncthreads();

    // ---------------- head: per-task gathered 2-layer MLP ----------------
    const int warp = tid >> 5, lane = tid & 31;
    for (int wt = warp; wt < 800; wt += NT / 32) {
        int c1 = wt >> 3, bb = wt & 7;
        int tk = __ldg(task_labels + b0 + bb);
        const float* W1r = hw1 + ((size_t)tk * 100 + c1) * 200;
        const float* fr  = &sm[OFF_FEAT + bb * 200];
        float acc = 0.f;
        for (int c2 = lane; c2 < 200; c2 += 32) acc = fmaf(fr[c2], __ldg(W1r + c2), acc);
        #pragma unroll
        for (int o = 16; o; o >>= 1) acc += __shfl_xor_sync(0xffffffffu, acc, o);
        if (lane == 0) sm[OFF_HF + bb * 100 + c1] = tanhf(acc + __ldg(hb1 + tk * 100 + c1));
    }
    __syncthreads();
    if (warp < BB) {
        int bb = warp;
        int tk = __ldg(task_labels + b0 + bb);
        const float* W2r = hw2 + tk * 100;
        float acc = 0.f;
        for (int c1 = lane; c1 < 100; c1 += 32)
            acc = fmaf(sm[OFF_HF + bb * 100 + c1], __ldg(W2r + c1), acc);
        #pragma unroll
        for (int o = 16; o; o >>= 1) acc += __shfl_xor_sync(0xffffffffu, acc, o);
        if (lane == 0) out[b0 + bb] = acc + __ldg(hb2 + tk);
    }
}

extern "C" void kernel_launch(void* const* d_in, const int* in_sizes, int n_in,
                              void* d_out, int out_size)
{
    const float* x    = (const float*)d_in[0];
    const int*   tl   = (const int*)  d_in[1];
    const float* w1_0 = (const float*)d_in[2];
    const float* b1_0 = (const float*)d_in[3];
    const float* w2_0 = (const float*)d_in[4];
    const float* b2_0 = (const float*)d_in[5];
    const float* wd_0 = (const float*)d_in[6];
    const float* bd_0 = (const float*)d_in[7];
    const float* w1_1 = (const float*)d_in[8];
    const float* b1_1 = (const float*)d_in[9];
    const float* w2_1 = (const float*)d_in[10];
    const float* b2_1 = (const float*)d_in[11];
    const float* wd_1 = (const float*)d_in[12];
    const float* bd_1 = (const float*)d_in[13];
    const float* hw1  = (const float*)d_in[14];
    const float* hb1  = (const float*)d_in[15];
    const float* hw2  = (const float*)d_in[16];
    const float* hb2  = (const float*)d_in[17];
    float* out = (float*)d_out;

    const int smem_bytes = SMEM_FLOATS * sizeof(float);
    cudaFuncSetAttribute(mga_kernel, cudaFuncAttributeMaxDynamicSharedMemorySize, smem_bytes);

    mga_kernel<<<4096 / BB, NT, smem_bytes>>>(
        x, tl, w1_0, b1_0, w2_0, b2_0, wd_0, bd_0,
        w1_1, b1_1, w2_1, b2_1, wd_1, bd_1,
        hw1, hb1, hw2, hb2, out);
}

// round 3
// speedup vs baseline: 1.6287x; 1.6287x over previous
#include <cuda_runtime.h>
#include <cstddef>
#include <cstdint>

// ---------------- gmem scratch (layout: [chan][t][batch], batch fastest) ----------------
__device__ float g_h1 [100 * 21 * 4096];
__device__ float g_y  [100 *  9 * 4096];
__device__ float g_h11[200 *  5 * 4096];

// ---------------- cp.async helpers ----------------
__device__ __forceinline__ void cp16(float* dst_smem, const float* src) {
    uint32_t s = (uint32_t)__cvta_generic_to_shared(dst_smem);
    asm volatile("cp.async.cg.shared.global [%0], [%1], 16;\n" :: "r"(s), "l"(src));
}
__device__ __forceinline__ void cp_commit() { asm volatile("cp.async.commit_group;\n"); }
__device__ __forceinline__ void cp_wait0()  { asm volatile("cp.async.wait_group 0;\n"); }

// =====================================================================================
// K1: h1[co][t][b] = relu(conv1_0(x)) at t_glob = 235..255 (t=0..20)
// block: 512 thr, 16 batches; grid 256
// =====================================================================================
__global__ __launch_bounds__(512, 1) void k1(
    const float* __restrict__ x, const float* __restrict__ w1_0, const float* __restrict__ b1_0)
{
    extern __shared__ float sm[];
    float* xs = sm;           // [(ci*25+tau)*16 + bl], 12000
    float* w  = sm + 12000;   // w1_0 full, 15000
    const int tid = threadIdx.x;
    const int b0  = blockIdx.x * 16;

    for (int i = tid; i < 12000; i += 512) {
        int ci = i / 400; int r = i - ci * 400; int bl = r / 25; int tau = r - bl * 25;
        xs[(ci * 25 + tau) * 16 + bl] = x[(size_t)(b0 + bl) * 7680 + ci * 256 + 231 + tau];
    }
    for (int i = tid; i < 15000; i += 512) w[i] = w1_0[i];
    __syncthreads();

    const int bl = tid & 15, cs = tid >> 4;
    for (int m = 0; m < 4; m++) {
        int co = cs + 32 * m;
        if (co >= 100) break;
        float acc[21];
        float bias = __ldg(b1_0 + co);
        #pragma unroll
        for (int t = 0; t < 21; t++) acc[t] = bias;
        for (int ci = 0; ci < 30; ci++) {
            float xw[25];
            const float* xp = &xs[(ci * 25) * 16 + bl];
            #pragma unroll
            for (int tau = 0; tau < 25; tau++) xw[tau] = xp[tau * 16];
            const float* wp = &w[co * 150 + ci * 5];
            #pragma unroll
            for (int k = 0; k < 5; k++) {
                float wv = wp[k];
                #pragma unroll
                for (int t = 0; t < 21; t++) acc[t] = fmaf(xw[t + k], wv, acc[t]);
            }
        }
        #pragma unroll
        for (int t = 0; t < 21; t++)
            g_h1[((size_t)co * 21 + t) * 4096 + b0 + bl] = fmaxf(acc[t], 0.f);
    }
}

// =====================================================================================
// K2: y[co][j][b] = relu(relu(conv2_0(h1)) + bd0 + wd0*x) at t_glob = 239+2j (j=0..8)
// conv uses h1 t-index 2j+k. double-buffered chunks over ci (6x16 + 4).
// =====================================================================================
#define K2_SH 5376   // 16*21*16
#define K2_SW 8000   // 100*80
__global__ __launch_bounds__(512, 1) void k2(
    const float* __restrict__ x,
    const float* __restrict__ w2_0, const float* __restrict__ b2_0,
    const float* __restrict__ wd_0, const float* __restrict__ bd_0)
{
    extern __shared__ float sm[];
    float* smh[2] = { sm, sm + K2_SH };
    float* smw[2] = { sm + 2 * K2_SH, sm + 2 * K2_SH + K2_SW };
    float* xs2    = sm + 2 * K2_SH + 2 * K2_SW;   // [(ci*16+bl)*9 + j], 4320
    const int tid = threadIdx.x;
    const int b0  = blockIdx.x * 16;
    const int bl  = tid & 15, cs = tid >> 4;

    for (int i = tid; i < 4320; i += 512) {
        int ci = i / 144; int r = i - ci * 144; int blx = r / 9; int j = r - blx * 9;
        xs2[(ci * 16 + blx) * 9 + j] = x[(size_t)(b0 + blx) * 7680 + ci * 256 + 239 + 2 * j];
    }

    int cov[4];
    #pragma unroll
    for (int m = 0; m < 4; m++) { int co = cs + 32 * m; cov[m] = (co < 100) ? co : 0; }
    float a[4][9];
    #pragma unroll
    for (int m = 0; m < 4; m++) {
        float bi = __ldg(b2_0 + cov[m]);
        #pragma unroll
        for (int j = 0; j < 9; j++) a[m][j] = bi;
    }

    // chunk loader
    auto load_chunk = [&](int p, int ci0, int C) {
        int nh = C * 84;                       // float4 count for h chunk
        for (int i = tid; i < nh; i += 512) {
            int cc = i / 84; int r = i - cc * 84; int t = r >> 2; int q = r & 3;
            cp16(&smh[p][(cc * 21 + t) * 16 + 4 * q],
                 &g_h1[((size_t)(ci0 + cc) * 21 + t) * 4096 + b0 + 4 * q]);
        }
        int per = (5 * C) >> 2;                // float4 per co row
        int nw = 100 * per;
        for (int i = tid; i < nw; i += 512) {
            int co = i / per; int q = i - co * per;
            cp16(&smw[p][co * 80 + 4 * q], &w2_0[co * 500 + ci0 * 5 + 4 * q]);
        }
        cp_commit();
    };

    load_chunk(0, 0, 16);
    int p = 0;
    for (int c = 0; c < 7; c++) {
        int C = (c == 6) ? 4 : 16;
        cp_wait0();
        __syncthreads();
        if (c + 1 < 7) load_chunk(p ^ 1, (c + 1) * 16, (c + 1 == 6) ? 4 : 16);
        const float* hB = smh[p];
        const float* wB = smw[p];
        for (int cc = 0; cc < C; cc++) {
            float hv[21];
            const float* hp = &hB[(cc * 21) * 16 + bl];
            #pragma unroll
            for (int t = 0; t < 21; t++) hv[t] = hp[t * 16];
            #pragma unroll
            for (int m = 0; m < 4; m++) {
                const float* wp = &wB[cov[m] * 80 + cc * 5];
                #pragma unroll
                for (int k = 0; k < 5; k++) {
                    float wv = wp[k];
                    #pragma unroll
                    for (int j = 0; j < 9; j++) a[m][j] = fmaf(hv[2 * j + k], wv, a[m][j]);
                }
            }
        }
        p ^= 1;
        if (c + 1 < 7) __syncthreads();
    }

    int nm = (cs < 4) ? 4 : 3;
    for (int m = 0; m < nm; m++) {
        int co = cov[m];
        float r9[9];
        float rb = __ldg(bd_0 + co);
        #pragma unroll
        for (int j = 0; j < 9; j++) r9[j] = fmaxf(a[m][j], 0.f) + rb;   // inner relu!
        for (int ci = 0; ci < 30; ci++) {
            float wv = __ldg(wd_0 + co * 30 + ci);
            const float* xp = &xs2[(ci * 16 + bl) * 9];
            #pragma unroll
            for (int j = 0; j < 9; j++) r9[j] = fmaf(xp[j], wv, r9[j]);
        }
        #pragma unroll
        for (int j = 0; j < 9; j++)
            g_y[((size_t)co * 9 + j) * 4096 + b0 + bl] = fmaxf(r9[j], 0.f);
    }
}

// =====================================================================================
// K3: h11[co2][i][b] = relu(conv1_1(y, dil=2)) at t_glob = 247+2i (i=0..4)
// conv uses y j-index i+k. chunks over ci (6x16 + 4).
// =====================================================================================
#define K3_SY 2304   // 16*9*16
#define K3_SW 16000  // 200*80
__global__ __launch_bounds__(512, 1) void k3(
    const float* __restrict__ w1_1, const float* __restrict__ b1_1)
{
    extern __shared__ float sm[];
    float* smy[2] = { sm, sm + K3_SY };
    float* smw[2] = { sm + 2 * K3_SY, sm + 2 * K3_SY + K3_SW };
    const int tid = threadIdx.x;
    const int b0  = blockIdx.x * 16;
    const int bl  = tid & 15, cs = tid >> 4;

    int cov[7];
    #pragma unroll
    for (int m = 0; m < 7; m++) { int co = cs + 32 * m; cov[m] = (co < 200) ? co : 0; }
    float a[7][5];
    #pragma unroll
    for (int m = 0; m < 7; m++) {
        float bi = __ldg(b1_1 + cov[m]);
        #pragma unroll
        for (int i = 0; i < 5; i++) a[m][i] = bi;
    }

    auto load_chunk = [&](int p, int ci0, int C) {
        int ny = C * 36;
        for (int i = tid; i < ny; i += 512) {
            int cc = i / 36; int r = i - cc * 36; int j = r >> 2; int q = r & 3;
            cp16(&smy[p][(cc * 9 + j) * 16 + 4 * q],
                 &g_y[((size_t)(ci0 + cc) * 9 + j) * 4096 + b0 + 4 * q]);
        }
        int per = (5 * C) >> 2;
        int nw = 200 * per;
        for (int i = tid; i < nw; i += 512) {
            int co = i / per; int q = i - co * per;
            cp16(&smw[p][co * 80 + 4 * q], &w1_1[co * 500 + ci0 * 5 + 4 * q]);
        }
        cp_commit();
    };

    load_chunk(0, 0, 16);
    int p = 0;
    for (int c = 0; c < 7; c++) {
        int C = (c == 6) ? 4 : 16;
        cp_wait0();
        __syncthreads();
        if (c + 1 < 7) load_chunk(p ^ 1, (c + 1) * 16, (c + 1 == 6) ? 4 : 16);
        const float* yB = smy[p];
        const float* wB = smw[p];
        for (int cc = 0; cc < C; cc++) {
            float yv[9];
            const float* yp = &yB[(cc * 9) * 16 + bl];
            #pragma unroll
            for (int j = 0; j < 9; j++) yv[j] = yp[j * 16];
            #pragma unroll
            for (int m = 0; m < 7; m++) {
                const float* wp = &wB[cov[m] * 80 + cc * 5];
                #pragma unroll
                for (int k = 0; k < 5; k++) {
                    float wv = wp[k];
                    #pragma unroll
                    for (int i = 0; i < 5; i++) a[m][i] = fmaf(yv[i + k], wv, a[m][i]);
                }
            }
        }
        p ^= 1;
        if (c + 1 < 7) __syncthreads();
    }

    int nm = (cs < 8) ? 7 : 6;
    for (int m = 0; m < nm; m++) {
        int co2 = cov[m];
        #pragma unroll
        for (int i = 0; i < 5; i++)
            g_h11[((size_t)co2 * 5 + i) * 4096 + b0 + bl] = fmaxf(a[m][i], 0.f);
    }
}

// =====================================================================================
// K4: feat = relu(relu(conv2_1(h11, dil=2)@t=255) + bd1 + wd1*y[t=255]), then fused head:
//     h = tanh(feat . hw1[task] + hb1[task]); out = h . hw2[task] + hb2[task]
// chunks over ci2 (12x16 + 8).
// =====================================================================================
#define K4_SH 1280   // 16*5*16
#define K4_SW 16000  // 200*80
__global__ __launch_bounds__(512, 1) void k4(
    const int* __restrict__ task_labels,
    const float* __restrict__ w2_1, const float* __restrict__ b2_1,
    const float* __restrict__ wd_1, const float* __restrict__ bd_1,
    const float* __restrict__ hw1, const float* __restrict__ hb1,
    const float* __restrict__ hw2, const float* __restrict__ hb2,
    float* __restrict__ out)
{
    extern __shared__ float sm[];
    float* smh[2] = { sm, sm + K4_SH };
    float* smw[2] = { sm + 2 * K4_SH, sm + 2 * K4_SH + K4_SW };
    float* yres = sm + 2 * K4_SH + 2 * K4_SW;     // [ci*16 + bl], 1600
    float* feat = yres + 1600;                    // [bl*201 + co2], 3216
    float* smH  = feat + 3216;                    // [bl*104 + c1], 1664
    const int tid = threadIdx.x;
    const int b0  = blockIdx.x * 16;
    const int bl  = tid & 15, cs = tid >> 4;

    for (int i = tid; i < 1600; i += 512) {
        int blx = i & 15; int ci = i >> 4;
        yres[ci * 16 + blx] = g_y[((size_t)ci * 9 + 8) * 4096 + b0 + blx];
    }

    int cov[7];
    #pragma unroll
    for (int m = 0; m < 7; m++) { int co = cs + 32 * m; cov[m] = (co < 200) ? co : 0; }
    float a[7];
    #pragma unroll
    for (int m = 0; m < 7; m++) a[m] = __ldg(b2_1 + cov[m]);

    auto load_chunk = [&](int p, int ci0, int C) {
        int nh = C * 20;
        for (int i = tid; i < nh; i += 512) {
            int cc = i / 20; int r = i - cc * 20; int k = r >> 2; int q = r & 3;
            cp16(&smh[p][(cc * 5 + k) * 16 + 4 * q],
                 &g_h11[((size_t)(ci0 + cc) * 5 + k) * 4096 + b0 + 4 * q]);
        }
        int per = (5 * C) >> 2;
        int nw = 200 * per;
        for (int i = tid; i < nw; i += 512) {
            int co = i / per; int q = i - co * per;
            cp16(&smw[p][co * 80 + 4 * q], &w2_1[co * 1000 + ci0 * 5 + 4 * q]);
        }
        cp_commit();
    };

    load_chunk(0, 0, 16);
    int p = 0;
    for (int c = 0; c < 13; c++) {
        int C = (c == 12) ? 8 : 16;
        cp_wait0();
        __syncthreads();
        if (c + 1 < 13) load_chunk(p ^ 1, (c + 1) * 16, (c + 1 == 12) ? 8 : 16);
        const float* hB = smh[p];
        const float* wB = smw[p];
        for (int cc = 0; cc < C; cc++) {
            float hv[5];
            const float* hp = &hB[(cc * 5) * 16 + bl];
            #pragma unroll
            for (int k = 0; k < 5; k++) hv[k] = hp[k * 16];
            #pragma unroll
            for (int m = 0; m < 7; m++) {
                const float* wp = &wB[cov[m] * 80 + cc * 5];
                #pragma unroll
                for (int k = 0; k < 5; k++) a[m] = fmaf(hv[k], wp[k], a[m]);
            }
        }
        p ^= 1;
        if (c + 1 < 13) __syncthreads();
    }

    int nm = (cs < 8) ? 7 : 6;
    for (int m = 0; m < nm; m++) {
        int co2 = cov[m];
        float v = fmaxf(a[m], 0.f) + __ldg(bd_1 + co2);   // inner relu!
        const float* wp = wd_1 + co2 * 100;
        for (int ci = 0; ci < 100; ci++)
            v = fmaf(yres[ci * 16 + bl], __ldg(wp + ci), v);
        feat[bl * 201 + co2] = fmaxf(v, 0.f);
    }
    __syncthreads();

    // ------------- head: one warp per batch element -------------
    const int w = tid >> 5, l = tid & 31;
    {
        int task = __ldg(task_labels + b0 + w);
        const float* fr = &feat[w * 201];
        for (int c1 = 0; c1 < 100; c1++) {
            const float* W1r = hw1 + ((size_t)task * 100 + c1) * 200;
            float acc = 0.f;
            #pragma unroll
            for (int q = 0; q < 7; q++) {
                int c2 = l + 32 * q;
                if (c2 < 200) acc = fmaf(fr[c2], __ldg(W1r + c2), acc);
            }
            #pragma unroll
            for (int o = 16; o; o >>= 1) acc += __shfl_xor_sync(0xffffffffu, acc, o);
            if (l == 0) smH[w * 104 + c1] = tanhf(acc + __ldg(hb1 + task * 100 + c1));
        }
        __syncwarp();
        const float* W2r = hw2 + task * 100;
        float acc = 0.f;
        #pragma unroll
        for (int q = 0; q < 4; q++) {
            int c1 = l + 32 * q;
            if (c1 < 100) acc = fmaf(smH[w * 104 + c1], __ldg(W2r + c1), acc);
        }
        #pragma unroll
        for (int o = 16; o; o >>= 1) acc += __shfl_xor_sync(0xffffffffu, acc, o);
        if (l == 0) out[b0 + w] = acc + __ldg(hb2 + task);
    }
}

// =====================================================================================
extern "C" void kernel_launch(void* const* d_in, const int* in_sizes, int n_in,
                              void* d_out, int out_size)
{
    const float* x    = (const float*)d_in[0];
    const int*   tl   = (const int*)  d_in[1];
    const float* w1_0 = (const float*)d_in[2];
    const float* b1_0 = (const float*)d_in[3];
    const float* w2_0 = (const float*)d_in[4];
    const float* b2_0 = (const float*)d_in[5];
    const float* wd_0 = (const float*)d_in[6];
    const float* bd_0 = (const float*)d_in[7];
    const float* w1_1 = (const float*)d_in[8];
    const float* b1_1 = (const float*)d_in[9];
    const float* w2_1 = (const float*)d_in[10];
    const float* b2_1 = (const float*)d_in[11];
    const float* wd_1 = (const float*)d_in[12];
    const float* bd_1 = (const float*)d_in[13];
    const float* hw1  = (const float*)d_in[14];
    const float* hb1  = (const float*)d_in[15];
    const float* hw2  = (const float*)d_in[16];
    const float* hb2  = (const float*)d_in[17];
    float* out = (float*)d_out;

    const int s1 = 27000 * 4;
    const int s2 = (2 * K2_SH + 2 * K2_SW + 4320) * 4;
    const int s3 = (2 * K3_SY + 2 * K3_SW) * 4;
    const int s4 = (2 * K4_SH + 2 * K4_SW + 1600 + 3216 + 1664) * 4;
    cudaFuncSetAttribute(k1, cudaFuncAttributeMaxDynamicSharedMemorySize, s1);
    cudaFuncSetAttribute(k2, cudaFuncAttributeMaxDynamicSharedMemorySize, s2);
    cudaFuncSetAttribute(k3, cudaFuncAttributeMaxDynamicSharedMemorySize, s3);
    cudaFuncSetAttribute(k4, cudaFuncAttributeMaxDynamicSharedMemorySize, s4);

    k1<<<256, 512, s1>>>(x, w1_0, b1_0);
    k2<<<256, 512, s2>>>(x, w2_0, b2_0, wd_0, bd_0);
    k3<<<256, 512, s3>>>(w1_1, b1_1);
    k4<<<256, 512, s4>>>(tl, w2_1, b2_1, wd_1, bd_1, hw1, hb1, hw2, hb2, out);
}

// round 5
// speedup vs baseline: 1.7471x; 1.0727x over previous
#include <cuda_runtime.h>
#include <cstddef>
#include <cstdint>

// ---------------- gmem scratch (layout: [chan][t][batch], batch fastest) ----------------
__device__ float g_h1 [100 * 21 * 4096];
__device__ float g_y  [100 *  9 * 4096];
__device__ float g_h11[200 *  5 * 4096];

// ---------------- helpers ----------------
__device__ __forceinline__ void cp16(float* dst_smem, const float* src) {
    uint32_t s = (uint32_t)__cvta_generic_to_shared(dst_smem);
    asm volatile("cp.async.cg.shared.global [%0], [%1], 16;\n" :: "r"(s), "l"(src));
}
__device__ __forceinline__ void cp_commit() { asm volatile("cp.async.commit_group;\n"); }
__device__ __forceinline__ void cp_wait0()  { asm volatile("cp.async.wait_group 0;\n"); }

// =====================================================================================
// K1: h1[co][t][b] = relu(conv1_0(x)) at t_glob = 235..255 (t=0..20)
// =====================================================================================
__global__ __launch_bounds__(512, 1) void k1(
    const float* __restrict__ x, const float* __restrict__ w1_0, const float* __restrict__ b1_0)
{
    extern __shared__ float sm[];
    float* xs = sm;           // [(ci*25+tau)*16 + bl], 12000
    float* w  = sm + 12000;   // w1_0 full, 15000
    const int tid = threadIdx.x;
    const int b0  = blockIdx.x * 16;

    for (int i = tid; i < 12000; i += 512) {
        int ci = i / 400; int r = i - ci * 400; int bl = r / 25; int tau = r - bl * 25;
        xs[(ci * 25 + tau) * 16 + bl] = x[(size_t)(b0 + bl) * 7680 + ci * 256 + 231 + tau];
    }
    for (int i = tid; i < 15000; i += 512) w[i] = w1_0[i];
    __syncthreads();

    const int bl = tid & 15, cs = tid >> 4;
    for (int m = 0; m < 4; m++) {
        int co = cs + 32 * m;
        if (co >= 100) break;
        float acc[21];
        float bias = __ldg(b1_0 + co);
        #pragma unroll
        for (int t = 0; t < 21; t++) acc[t] = bias;
        for (int ci = 0; ci < 30; ci++) {
            float xw[25];
            const float* xp = &xs[(ci * 25) * 16 + bl];
            #pragma unroll
            for (int tau = 0; tau < 25; tau++) xw[tau] = xp[tau * 16];
            const float* wp = &w[co * 150 + ci * 5];
            #pragma unroll
            for (int k = 0; k < 5; k++) {
                float wv = wp[k];
                #pragma unroll
                for (int t = 0; t < 21; t++) acc[t] = fmaf(xw[t + k], wv, acc[t]);
            }
        }
        #pragma unroll
        for (int t = 0; t < 21; t++)
            g_h1[((size_t)co * 21 + t) * 4096 + b0 + bl] = fmaxf(acc[t], 0.f);
    }
}

// =====================================================================================
// K2: y[co][j][b] = relu(relu(conv2_0(h1)) + bd0 + wd0*x) at t_glob = 239+2j (j=0..8)
// Full h1 tile in smem; weights double-buffered in chunks over ci.
// =====================================================================================
#define K2_H  33600                 // h1 tile [ci][t][bl] 100*21*16
#define K2_X  4320                  // xs2 [(ci*16+bl)*9 + j]
#define K2_WB 8000                  // weight buffer (100 co x 80)
__global__ __launch_bounds__(512, 1) void k2(
    const float* __restrict__ x,
    const float* __restrict__ w2_0, const float* __restrict__ b2_0,
    const float* __restrict__ wd_0, const float* __restrict__ bd_0)
{
    extern __shared__ float sm[];
    float* h1s    = sm;                        // K2_H
    float* xs2    = sm + K2_H;                 // K2_X
    float* wb[2]  = { sm + K2_H + K2_X, sm + K2_H + K2_X + K2_WB };
    const int tid = threadIdx.x;
    const int b0  = blockIdx.x * 16;
    const int bl  = tid & 15, cs = tid >> 4;

    for (int i = tid; i < 8400; i += 512) {          // 33600/4 float4s
        int cit = i >> 2, q = i & 3;
        cp16(&h1s[cit * 16 + 4 * q], &g_h1[(size_t)cit * 4096 + b0 + 4 * q]);
    }
    for (int i = tid; i < 2000; i += 512) {          // chunk 0
        int co = i / 20, q = i - co * 20;
        cp16(&wb[0][co * 80 + 4 * q], &w2_0[co * 500 + 4 * q]);
    }
    cp_commit();

    for (int i = tid; i < K2_X; i += 512) {
        int ci = i / 144; int r = i - ci * 144; int blx = r / 9; int j = r - blx * 9;
        xs2[(ci * 16 + blx) * 9 + j] = x[(size_t)(b0 + blx) * 7680 + ci * 256 + 239 + 2 * j];
    }

    int cov[4];
    #pragma unroll
    for (int m = 0; m < 4; m++) { int co = cs + 32 * m; cov[m] = (co < 100) ? co : 0; }
    float a[4][9];
    #pragma unroll
    for (int m = 0; m < 4; m++) {
        float bi = __ldg(b2_0 + cov[m]);
        #pragma unroll
        for (int j = 0; j < 9; j++) a[m][j] = bi;
    }

    cp_wait0();
    __syncthreads();

    int p = 0;
    for (int c = 0; c < 7; c++) {
        int ci0 = c * 16;
        int C = (c == 6) ? 4 : 16;
        if (c + 1 < 7) {
            int nci0 = (c + 1) * 16;
            int nC = (c + 1 == 6) ? 4 : 16;
            int per = (5 * nC) >> 2;
            int nw = 100 * per;
            for (int i = tid; i < nw; i += 512) {
                int co = i / per, q = i - co * per;
                cp16(&wb[p ^ 1][co * 80 + 4 * q], &w2_0[co * 500 + nci0 * 5 + 4 * q]);
            }
            cp_commit();
        }
        const float* wB = wb[p];
        for (int cc = 0; cc < C; cc++) {
            float hv[21];
            const float* hp = &h1s[((ci0 + cc) * 21) * 16 + bl];
            #pragma unroll
            for (int t = 0; t < 21; t++) hv[t] = hp[t * 16];
            #pragma unroll
            for (int m = 0; m < 4; m++) {
                const float* wp = &wB[cov[m] * 80 + cc * 5];
                #pragma unroll
                for (int k = 0; k < 5; k++) {
                    float wv = wp[k];
                    #pragma unroll
                    for (int j = 0; j < 9; j++) a[m][j] = fmaf(hv[2 * j + k], wv, a[m][j]);
                }
            }
        }
        if (c + 1 < 7) { cp_wait0(); __syncthreads(); p ^= 1; }
    }

    int nm = (cs < 4) ? 4 : 3;
    for (int m = 0; m < nm; m++) {
        int co = cov[m];
        float r9[9];
        float rb = __ldg(bd_0 + co);
        #pragma unroll
        for (int j = 0; j < 9; j++) r9[j] = fmaxf(a[m][j], 0.f) + rb;   // inner relu
        for (int ci = 0; ci < 30; ci++) {
            float wv = __ldg(wd_0 + co * 30 + ci);
            const float* xp = &xs2[(ci * 16 + bl) * 9];
            #pragma unroll
            for (int j = 0; j < 9; j++) r9[j] = fmaf(xp[j], wv, r9[j]);
        }
        #pragma unroll
        for (int j = 0; j < 9; j++)
            g_y[((size_t)co * 9 + j) * 4096 + b0 + bl] = fmaxf(r9[j], 0.f);
    }
}

// =====================================================================================
// K3: h11[co2][i][b] = relu(conv1_1(y, dil=2)) at t_glob = 247+2i (i=0..4)
// =====================================================================================
#define K3_Y  14400                 // y tile [ci][j][bl] 100*9*16
#define K3_WB 16000                 // 200 co2 x 80
__global__ __launch_bounds__(512, 1) void k3(
    const float* __restrict__ w1_1, const float* __restrict__ b1_1)
{
    extern __shared__ float sm[];
    float* ys    = sm;
    float* wb[2] = { sm + K3_Y, sm + K3_Y + K3_WB };
    const int tid = threadIdx.x;
    const int b0  = blockIdx.x * 16;
    const int bl  = tid & 15, cs = tid >> 4;

    for (int i = tid; i < 3600; i += 512) {          // 14400/4
        int cij = i >> 2, q = i & 3;
        cp16(&ys[cij * 16 + 4 * q], &g_y[(size_t)cij * 4096 + b0 + 4 * q]);
    }
    for (int i = tid; i < 4000; i += 512) {          // chunk 0
        int co = i / 20, q = i - co * 20;
        cp16(&wb[0][co * 80 + 4 * q], &w1_1[co * 500 + 4 * q]);
    }
    cp_commit();

    int cov[7];
    #pragma unroll
    for (int m = 0; m < 7; m++) { int co = cs + 32 * m; cov[m] = (co < 200) ? co : 0; }
    float a[7][5];
    #pragma unroll
    for (int m = 0; m < 7; m++) {
        float bi = __ldg(b1_1 + cov[m]);
        #pragma unroll
        for (int i = 0; i < 5; i++) a[m][i] = bi;
    }

    cp_wait0();
    __syncthreads();

    int p = 0;
    for (int c = 0; c < 7; c++) {
        int ci0 = c * 16;
        int C = (c == 6) ? 4 : 16;
        if (c + 1 < 7) {
            int nci0 = (c + 1) * 16;
            int nC = (c + 1 == 6) ? 4 : 16;
            int per = (5 * nC) >> 2;
            int nw = 200 * per;
            for (int i = tid; i < nw; i += 512) {
                int co = i / per, q = i - co * per;
                cp16(&wb[p ^ 1][co * 80 + 4 * q], &w1_1[co * 500 + nci0 * 5 + 4 * q]);
            }
            cp_commit();
        }
        const float* wB = wb[p];
        for (int cc = 0; cc < C; cc++) {
            float yv[9];
            const float* yp = &ys[((ci0 + cc) * 9) * 16 + bl];
            #pragma unroll
            for (int j = 0; j < 9; j++) yv[j] = yp[j * 16];
            #pragma unroll
            for (int m = 0; m < 7; m++) {
                const float* wp = &wB[cov[m] * 80 + cc * 5];
                #pragma unroll
                for (int k = 0; k < 5; k++) {
                    float wv = wp[k];
                    #pragma unroll
                    for (int i = 0; i < 5; i++) a[m][i] = fmaf(yv[i + k], wv, a[m][i]);
                }
            }
        }
        if (c + 1 < 7) { cp_wait0(); __syncthreads(); p ^= 1; }
    }

    int nm = (cs < 8) ? 7 : 6;
    for (int m = 0; m < nm; m++) {
        int co2 = cov[m];
        #pragma unroll
        for (int i = 0; i < 5; i++)
            g_h11[((size_t)co2 * 5 + i) * 4096 + b0 + bl] = fmaxf(a[m][i], 0.f);
    }
}

// =====================================================================================
// K4: feat = relu(relu(conv2_1(h11, dil=2)@t=255) + bd1 + wd1*y[t=255]); fused head.
// Head: one thread per (bl,c1) output — no warp reductions, hw1 rows via float4.
// =====================================================================================
#define K4_H   16000                // h11 tile [ci2][k][bl] 200*5*16
#define K4_YR  1600                 // yres [ci*16+bl]
#define K4_FT  3216                 // feat [bl*201+co2]
#define K4_HH  1664                 // smH  [bl*104+c1]
#define K4_WB  16000                // 200 co2 x 80
__global__ __launch_bounds__(512, 1) void k4(
    const int* __restrict__ task_labels,
    const float* __restrict__ w2_1, const float* __restrict__ b2_1,
    const float* __restrict__ wd_1, const float* __restrict__ bd_1,
    const float* __restrict__ hw1, const float* __restrict__ hb1,
    const float* __restrict__ hw2, const float* __restrict__ hb2,
    float* __restrict__ out)
{
    extern __shared__ float sm[];
    float* h11s  = sm;                                  // K4_H
    float* yres  = sm + K4_H;                           // K4_YR
    float* feat  = sm + K4_H + K4_YR;                   // K4_FT
    float* smH   = sm + K4_H + K4_YR + K4_FT;           // K4_HH
    float* wb[2] = { sm + K4_H + K4_YR + K4_FT + K4_HH,
                     sm + K4_H + K4_YR + K4_FT + K4_HH + K4_WB };
    const int tid = threadIdx.x;
    const int b0  = blockIdx.x * 16;
    const int bl  = tid & 15, cs = tid >> 4;

    for (int i = tid; i < 4000; i += 512) {             // h11 tile: 16000/4
        int cik = i >> 2, q = i & 3;
        cp16(&h11s[cik * 16 + 4 * q], &g_h11[(size_t)cik * 4096 + b0 + 4 * q]);
    }
    for (int i = tid; i < 4000; i += 512) {             // weight chunk 0
        int co = i / 20, q = i - co * 20;
        cp16(&wb[0][co * 80 + 4 * q], &w2_1[co * 1000 + 4 * q]);
    }
    cp_commit();

    for (int i = tid; i < K4_YR; i += 512) {
        int blx = i & 15, ci = i >> 4;
        yres[ci * 16 + blx] = g_y[((size_t)ci * 9 + 8) * 4096 + b0 + blx];
    }

    int cov[7];
    #pragma unroll
    for (int m = 0; m < 7; m++) { int co = cs + 32 * m; cov[m] = (co < 200) ? co : 0; }
    float a[7];
    #pragma unroll
    for (int m = 0; m < 7; m++) a[m] = __ldg(b2_1 + cov[m]);

    cp_wait0();
    __syncthreads();

    int p = 0;
    for (int c = 0; c < 13; c++) {
        int ci0 = c * 16;
        int C = (c == 12) ? 8 : 16;
        if (c + 1 < 13) {
            int nci0 = (c + 1) * 16;
            int nC = (c + 1 == 12) ? 8 : 16;
            int per = (5 * nC) >> 2;
            int nw = 200 * per;
            for (int i = tid; i < nw; i += 512) {
                int co = i / per, q = i - co * per;
                cp16(&wb[p ^ 1][co * 80 + 4 * q], &w2_1[co * 1000 + nci0 * 5 + 4 * q]);
            }
            cp_commit();
        }
        const float* wB = wb[p];
        for (int cc = 0; cc < C; cc++) {
            float hv[5];
            const float* hp = &h11s[((ci0 + cc) * 5) * 16 + bl];
            #pragma unroll
            for (int k = 0; k < 5; k++) hv[k] = hp[k * 16];
            #pragma unroll
            for (int m = 0; m < 7; m++) {
                const float* wp = &wB[cov[m] * 80 + cc * 5];
                #pragma unroll
                for (int k = 0; k < 5; k++) a[m] = fmaf(hv[k], wp[k], a[m]);
            }
        }
        if (c + 1 < 13) { cp_wait0(); __syncthreads(); p ^= 1; }
    }

    // residual (4-way partials) + inner/outer relu
    int nm = (cs < 8) ? 7 : 6;
    for (int m = 0; m < nm; m++) {
        int co2 = cov[m];
        float v0 = fmaxf(a[m], 0.f) + __ldg(bd_1 + co2);   // inner relu
        float v1 = 0.f, v2 = 0.f, v3 = 0.f;
        const float* wp = wd_1 + co2 * 100;
        for (int ci = 0; ci < 100; ci += 4) {
            v0 = fmaf(yres[(ci + 0) * 16 + bl], __ldg(wp + ci + 0), v0);
            v1 = fmaf(yres[(ci + 1) * 16 + bl], __ldg(wp + ci + 1), v1);
            v2 = fmaf(yres[(ci + 2) * 16 + bl], __ldg(wp + ci + 2), v2);
            v3 = fmaf(yres[(ci + 3) * 16 + bl], __ldg(wp + ci + 3), v3);
        }
        feat[bl * 201 + co2] = fmaxf((v0 + v1) + (v2 + v3), 0.f);
    }
    __syncthreads();

    // ------------- head stage A: one thread per (bl, c1) output -------------
    for (int o = tid; o < 1600; o += 512) {
        int blx = o & 15, c1 = o >> 4;
        int task = __ldg(task_labels + b0 + blx);
        const float4* W = (const float4*)(hw1 + ((size_t)task * 100 + c1) * 200);
        const float* fr = &feat[blx * 201];
        float a0 = 0.f, a1 = 0.f, a2 = 0.f, a3 = 0.f;
        #pragma unroll 5
        for (int q = 0; q < 50; q++) {
            float4 wv = __ldg(W + q);
            a0 = fmaf(fr[4 * q + 0], wv.x, a0);
            a1 = fmaf(fr[4 * q + 1], wv.y, a1);
            a2 = fmaf(fr[4 * q + 2], wv.z, a2);
            a3 = fmaf(fr[4 * q + 3], wv.w, a3);
        }
        smH[blx * 104 + c1] = tanhf((a0 + a1) + (a2 + a3) + __ldg(hb1 + task * 100 + c1));
    }
    __syncthreads();

    // ------------- head stage B: one thread per batch element -------------
    if (tid < 16) {
        int blx = tid;
        int task = __ldg(task_labels + b0 + blx);
        const float4* W = (const float4*)(hw2 + task * 100);
        const float* hr = &smH[blx * 104];
        float a0 = 0.f, a1 = 0.f, a2 = 0.f, a3 = 0.f;
        #pragma unroll 5
        for (int q = 0; q < 25; q++) {
            float4 wv = __ldg(W + q);
            a0 = fmaf(hr[4 * q + 0], wv.x, a0);
            a1 = fmaf(hr[4 * q + 1], wv.y, a1);
            a2 = fmaf(hr[4 * q + 2], wv.z, a2);
            a3 = fmaf(hr[4 * q + 3], wv.w, a3);
        }
        out[b0 + blx] = (a0 + a1) + (a2 + a3) + __ldg(hb2 + task);
    }
}

// =====================================================================================
extern "C" void kernel_launch(void* const* d_in, const int* in_sizes, int n_in,
                              void* d_out, int out_size)
{
    const float* x    = (const float*)d_in[0];
    const int*   tl   = (const int*)  d_in[1];
    const float* w1_0 = (const float*)d_in[2];
    const float* b1_0 = (const float*)d_in[3];
    const float* w2_0 = (const float*)d_in[4];
    const float* b2_0 = (const float*)d_in[5];
    const float* wd_0 = (const float*)d_in[6];
    const float* bd_0 = (const float*)d_in[7];
    const float* w1_1 = (const float*)d_in[8];
    const float* b1_1 = (const float*)d_in[9];
    const float* w2_1 = (const float*)d_in[10];
    const float* b2_1 = (const float*)d_in[11];
    const float* wd_1 = (const float*)d_in[12];
    const float* bd_1 = (const float*)d_in[13];
    const float* hw1  = (const float*)d_in[14];
    const float* hb1  = (const float*)d_in[15];
    const float* hw2  = (const float*)d_in[16];
    const float* hb2  = (const float*)d_in[17];
    float* out = (float*)d_out;

    const int s1 = 27000 * 4;
    const int s2 = (K2_H + K2_X + 2 * K2_WB) * 4;
    const int s3 = (K3_Y + 2 * K3_WB) * 4;
    const int s4 = (K4_H + K4_YR + K4_FT + K4_HH + 2 * K4_WB) * 4;
    cudaFuncSetAttribute(k1, cudaFuncAttributeMaxDynamicSharedMemorySize, s1);
    cudaFuncSetAttribute(k2, cudaFuncAttributeMaxDynamicSharedMemorySize, s2);
    cudaFuncSetAttribute(k3, cudaFuncAttributeMaxDynamicSharedMemorySize, s3);
    cudaFuncSetAttribute(k4, cudaFuncAttributeMaxDynamicSharedMemorySize, s4);

    k1<<<256, 512, s1>>>(x, w1_0, b1_0);
    k2<<<256, 512, s2>>>(x, w2_0, b2_0, wd_0, bd_0);
    k3<<<256, 512, s3>>>(w1_1, b1_1);
    k4<<<256, 512, s4>>>(tl, w2_1, b2_1, wd_1, bd_1, hw1, hb1, hw2, hb2, out);
}

// round 6
// speedup vs baseline: 1.9974x; 1.1433x over previous
#include <cuda_runtime.h>
#include <cstddef>
#include <cstdint>

// ---------------- gmem scratch (layout: [chan][t][batch], batch fastest) ----------------
__device__ float g_h1 [100 * 21 * 4096];
__device__ float g_y  [100 *  9 * 4096];
__device__ float g_h11[200 *  5 * 4096];

// ---------------- helpers ----------------
__device__ __forceinline__ void cp16(float* dst_smem, const float* src) {
    uint32_t s = (uint32_t)__cvta_generic_to_shared(dst_smem);
    asm volatile("cp.async.cg.shared.global [%0], [%1], 16;\n" :: "r"(s), "l"(src));
}
__device__ __forceinline__ void cp_commit() { asm volatile("cp.async.commit_group;\n"); }
__device__ __forceinline__ void cp_wait0()  { asm volatile("cp.async.wait_group 0;\n"); }

// =====================================================================================
// K1: h1[co][t][b] = relu(conv1_0(x)) at t_glob = 235..255 (t=0..20)
// =====================================================================================
__global__ __launch_bounds__(512, 1) void k1(
    const float* __restrict__ x, const float* __restrict__ w1_0, const float* __restrict__ b1_0)
{
    extern __shared__ float sm[];
    float* xs = sm;           // [(ci*25+tau)*16 + bl], 12000
    float* w  = sm + 12000;   // w1_0 full, 15000
    const int tid = threadIdx.x;
    const int b0  = blockIdx.x * 16;

    for (int i = tid; i < 12000; i += 512) {
        int ci = i / 400; int r = i - ci * 400; int bl = r / 25; int tau = r - bl * 25;
        xs[(ci * 25 + tau) * 16 + bl] = x[(size_t)(b0 + bl) * 7680 + ci * 256 + 231 + tau];
    }
    for (int i = tid; i < 15000; i += 512) w[i] = w1_0[i];
    __syncthreads();

    const int bl = tid & 15, cs = tid >> 4;
    for (int m = 0; m < 4; m++) {
        int co = cs + 32 * m;
        if (co >= 100) break;
        float acc[21];
        float bias = __ldg(b1_0 + co);
        #pragma unroll
        for (int t = 0; t < 21; t++) acc[t] = bias;
        for (int ci = 0; ci < 30; ci++) {
            float xw[25];
            const float* xp = &xs[(ci * 25) * 16 + bl];
            #pragma unroll
            for (int tau = 0; tau < 25; tau++) xw[tau] = xp[tau * 16];
            const float* wp = &w[co * 150 + ci * 5];
            #pragma unroll
            for (int k = 0; k < 5; k++) {
                float wv = wp[k];
                #pragma unroll
                for (int t = 0; t < 21; t++) acc[t] = fmaf(xw[t + k], wv, acc[t]);
            }
        }
        #pragma unroll
        for (int t = 0; t < 21; t++)
            g_h1[((size_t)co * 21 + t) * 4096 + b0 + bl] = fmaxf(acc[t], 0.f);
    }
}

// =====================================================================================
// K2: y[co][j][b] = relu(relu(conv2_0(h1)) + bd0 + wd0*x) at t_glob = 239+2j (j=0..8)
// =====================================================================================
#define K2_H  33600
#define K2_X  4320
#define K2_WB 8000
__global__ __launch_bounds__(512, 1) void k2(
    const float* __restrict__ x,
    const float* __restrict__ w2_0, const float* __restrict__ b2_0,
    const float* __restrict__ wd_0, const float* __restrict__ bd_0)
{
    extern __shared__ float sm[];
    float* h1s    = sm;
    float* xs2    = sm + K2_H;
    float* wb[2]  = { sm + K2_H + K2_X, sm + K2_H + K2_X + K2_WB };
    const int tid = threadIdx.x;
    const int b0  = blockIdx.x * 16;
    const int bl  = tid & 15, cs = tid >> 4;

    for (int i = tid; i < 8400; i += 512) {
        int cit = i >> 2, q = i & 3;
        cp16(&h1s[cit * 16 + 4 * q], &g_h1[(size_t)cit * 4096 + b0 + 4 * q]);
    }
    for (int i = tid; i < 2000; i += 512) {
        int co = i / 20, q = i - co * 20;
        cp16(&wb[0][co * 80 + 4 * q], &w2_0[co * 500 + 4 * q]);
    }
    cp_commit();

    for (int i = tid; i < K2_X; i += 512) {
        int ci = i / 144; int r = i - ci * 144; int blx = r / 9; int j = r - blx * 9;
        xs2[(ci * 16 + blx) * 9 + j] = x[(size_t)(b0 + blx) * 7680 + ci * 256 + 239 + 2 * j];
    }

    int cov[4];
    #pragma unroll
    for (int m = 0; m < 4; m++) { int co = cs + 32 * m; cov[m] = (co < 100) ? co : 0; }
    float a[4][9];
    #pragma unroll
    for (int m = 0; m < 4; m++) {
        float bi = __ldg(b2_0 + cov[m]);
        #pragma unroll
        for (int j = 0; j < 9; j++) a[m][j] = bi;
    }

    cp_wait0();
    __syncthreads();

    int p = 0;
    for (int c = 0; c < 7; c++) {
        int ci0 = c * 16;
        int C = (c == 6) ? 4 : 16;
        if (c + 1 < 7) {
            int nci0 = (c + 1) * 16;
            int nC = (c + 1 == 6) ? 4 : 16;
            int per = (5 * nC) >> 2;
            int nw = 100 * per;
            for (int i = tid; i < nw; i += 512) {
                int co = i / per, q = i - co * per;
                cp16(&wb[p ^ 1][co * 80 + 4 * q], &w2_0[co * 500 + nci0 * 5 + 4 * q]);
            }
            cp_commit();
        }
        const float* wB = wb[p];
        for (int cc = 0; cc < C; cc++) {
            float hv[21];
            const float* hp = &h1s[((ci0 + cc) * 21) * 16 + bl];
            #pragma unroll
            for (int t = 0; t < 21; t++) hv[t] = hp[t * 16];
            #pragma unroll
            for (int m = 0; m < 4; m++) {
                const float* wp = &wB[cov[m] * 80 + cc * 5];
                #pragma unroll
                for (int k = 0; k < 5; k++) {
                    float wv = wp[k];
                    #pragma unroll
                    for (int j = 0; j < 9; j++) a[m][j] = fmaf(hv[2 * j + k], wv, a[m][j]);
                }
            }
        }
        if (c + 1 < 7) { cp_wait0(); __syncthreads(); p ^= 1; }
    }

    int nm = (cs < 4) ? 4 : 3;
    for (int m = 0; m < nm; m++) {
        int co = cov[m];
        float r9[9];
        float rb = __ldg(bd_0 + co);
        #pragma unroll
        for (int j = 0; j < 9; j++) r9[j] = fmaxf(a[m][j], 0.f) + rb;   // inner relu
        for (int ci = 0; ci < 30; ci++) {
            float wv = __ldg(wd_0 + co * 30 + ci);
            const float* xp = &xs2[(ci * 16 + bl) * 9];
            #pragma unroll
            for (int j = 0; j < 9; j++) r9[j] = fmaf(xp[j], wv, r9[j]);
        }
        #pragma unroll
        for (int j = 0; j < 9; j++)
            g_y[((size_t)co * 9 + j) * 4096 + b0 + bl] = fmaxf(r9[j], 0.f);
    }
}

// =====================================================================================
// K3: h11[co2][i][b] = relu(conv1_1(y, dil=2)) at t_glob = 247+2i (i=0..4)
// =====================================================================================
#define K3_Y  14400
#define K3_WB 16000
__global__ __launch_bounds__(512, 1) void k3(
    const float* __restrict__ w1_1, const float* __restrict__ b1_1)
{
    extern __shared__ float sm[];
    float* ys    = sm;
    float* wb[2] = { sm + K3_Y, sm + K3_Y + K3_WB };
    const int tid = threadIdx.x;
    const int b0  = blockIdx.x * 16;
    const int bl  = tid & 15, cs = tid >> 4;

    for (int i = tid; i < 3600; i += 512) {
        int cij = i >> 2, q = i & 3;
        cp16(&ys[cij * 16 + 4 * q], &g_y[(size_t)cij * 4096 + b0 + 4 * q]);
    }
    for (int i = tid; i < 4000; i += 512) {
        int co = i / 20, q = i - co * 20;
        cp16(&wb[0][co * 80 + 4 * q], &w1_1[co * 500 + 4 * q]);
    }
    cp_commit();

    int cov[7];
    #pragma unroll
    for (int m = 0; m < 7; m++) { int co = cs + 32 * m; cov[m] = (co < 200) ? co : 0; }
    float a[7][5];
    #pragma unroll
    for (int m = 0; m < 7; m++) {
        float bi = __ldg(b1_1 + cov[m]);
        #pragma unroll
        for (int i = 0; i < 5; i++) a[m][i] = bi;
    }

    cp_wait0();
    __syncthreads();

    int p = 0;
    for (int c = 0; c < 7; c++) {
        int ci0 = c * 16;
        int C = (c == 6) ? 4 : 16;
        if (c + 1 < 7) {
            int nci0 = (c + 1) * 16;
            int nC = (c + 1 == 6) ? 4 : 16;
            int per = (5 * nC) >> 2;
            int nw = 200 * per;
            for (int i = tid; i < nw; i += 512) {
                int co = i / per, q = i - co * per;
                cp16(&wb[p ^ 1][co * 80 + 4 * q], &w1_1[co * 500 + nci0 * 5 + 4 * q]);
            }
            cp_commit();
        }
        const float* wB = wb[p];
        for (int cc = 0; cc < C; cc++) {
            float yv[9];
            const float* yp = &ys[((ci0 + cc) * 9) * 16 + bl];
            #pragma unroll
            for (int j = 0; j < 9; j++) yv[j] = yp[j * 16];
            #pragma unroll
            for (int m = 0; m < 7; m++) {
                const float* wp = &wB[cov[m] * 80 + cc * 5];
                #pragma unroll
                for (int k = 0; k < 5; k++) {
                    float wv = wp[k];
                    #pragma unroll
                    for (int i = 0; i < 5; i++) a[m][i] = fmaf(yv[i + k], wv, a[m][i]);
                }
            }
        }
        if (c + 1 < 7) { cp_wait0(); __syncthreads(); p ^= 1; }
    }

    int nm = (cs < 8) ? 7 : 6;
    for (int m = 0; m < nm; m++) {
        int co2 = cov[m];
        #pragma unroll
        for (int i = 0; i < 5; i++)
            g_h11[((size_t)co2 * 5 + i) * 4096 + b0 + bl] = fmaxf(a[m][i], 0.f);
    }
}

// =====================================================================================
// K4: feat = relu(relu(conv2_1(h11)@t=255) + bd1 + wd1*y[t=255]); fused head.
// GEMM microkernel: 4co x 4b register tile, float4 operands, ci-split x2 + smem reduce.
// =====================================================================================
#define K4_H    16000               // h11 tile [cik][16b]  (cik = ci2*5+k, 1000 rows)
#define K4_YR   1600                // yres [ci*16+b]
#define K4_FT   3216                // feat [b*201+co2]
#define K4_HH   1664                // smH  [b*104+c1]
#define K4_WST  84                  // weight row stride (bank-conflict-free: 84%32=20)
#define K4_WB   (200 * K4_WST)      // 16800 floats per buffer
// conv/res partials alias the h11 tile region (dead after mainloop): 2*3200 each
__global__ __launch_bounds__(512, 1) void k4(
    const int* __restrict__ task_labels,
    const float* __restrict__ w2_1, const float* __restrict__ b2_1,
    const float* __restrict__ wd_1, const float* __restrict__ bd_1,
    const float* __restrict__ hw1, const float* __restrict__ hb1,
    const float* __restrict__ hw2, const float* __restrict__ hb2,
    float* __restrict__ out)
{
    extern __shared__ float sm[];
    float* h11s  = sm;                                  // K4_H
    float* convp = sm;                                  // alias: [s*3200 + co*16 + b]
    float* resp  = sm + 6400;                           // alias: [s*3200 + co*16 + b]
    float* yres  = sm + K4_H;                           // K4_YR
    float* feat  = sm + K4_H + K4_YR;                   // K4_FT
    float* smH   = sm + K4_H + K4_YR + K4_FT;           // K4_HH
    float* wb[2] = { sm + K4_H + K4_YR + K4_FT + K4_HH,
                     sm + K4_H + K4_YR + K4_FT + K4_HH + K4_WB };
    const int tid = threadIdx.x;
    const int b0  = blockIdx.x * 16;

    const int s   = tid >> 8;          // ci-half 0/1
    const int r   = tid & 255;
    const int cog = r >> 2;            // 0..63 (active < 50)
    const int bg  = r & 3;             // batch group (4 batches)
    const bool act = (cog < 50);
    const int cob = cog * 4;

    // stage h11 tile + weight chunk 0
    for (int i = tid; i < 4000; i += 512) {
        int cik = i >> 2, q = i & 3;
        cp16(&h11s[cik * 16 + 4 * q], &g_h11[(size_t)cik * 4096 + b0 + 4 * q]);
    }
    for (int i = tid; i < 4000; i += 512) {             // 200 rows x 20 float4
        int co = i / 20, q = i - co * 20;
        cp16(&wb[0][co * K4_WST + 4 * q], &w2_1[co * 1000 + 4 * q]);
    }
    cp_commit();

    for (int i = tid; i < K4_YR; i += 512) {
        int blx = i & 15, ci = i >> 4;
        yres[ci * 16 + blx] = g_y[((size_t)ci * 9 + 8) * 4096 + b0 + blx];
    }

    float acc[4][4];
    #pragma unroll
    for (int o = 0; o < 4; o++)
        #pragma unroll
        for (int b = 0; b < 4; b++) acc[o][b] = 0.f;

    cp_wait0();
    __syncthreads();

    int p = 0;
    for (int c = 0; c < 13; c++) {
        int C = (c == 12) ? 8 : 16;
        if (c + 1 < 13) {
            int nC = (c + 1 == 12) ? 8 : 16;
            int per = (5 * nC) >> 2;
            int nw = 200 * per;
            for (int i = tid; i < nw; i += 512) {
                int co = i / per, q = i - co * per;
                cp16(&wb[p ^ 1][co * K4_WST + 4 * q], &w2_1[co * 1000 + (c + 1) * 80 + 4 * q]);
            }
            cp_commit();
        }
        if (act) {
            const float* wB = wb[p];
            const int half = (5 * C) >> 1;              // 40 or 20
            const int lbase = s * half;
            const int gbase = c * 80;
            for (int st = 0; st < half; st += 4) {
                int l = lbase + st;
                int cik = gbase + l;
                float4 av0 = *(const float4*)&h11s[(cik + 0) * 16 + bg * 4];
                float4 av1 = *(const float4*)&h11s[(cik + 1) * 16 + bg * 4];
                float4 av2 = *(const float4*)&h11s[(cik + 2) * 16 + bg * 4];
                float4 av3 = *(const float4*)&h11s[(cik + 3) * 16 + bg * 4];
                #pragma unroll
                for (int o = 0; o < 4; o++) {
                    float4 wv = *(const float4*)&wB[(cob + o) * K4_WST + l];
                    acc[o][0] = fmaf(wv.x, av0.x, acc[o][0]);
                    acc[o][1] = fmaf(wv.x, av0.y, acc[o][1]);
                    acc[o][2] = fmaf(wv.x, av0.z, acc[o][2]);
                    acc[o][3] = fmaf(wv.x, av0.w, acc[o][3]);
                    acc[o][0] = fmaf(wv.y, av1.x, acc[o][0]);
                    acc[o][1] = fmaf(wv.y, av1.y, acc[o][1]);
                    acc[o][2] = fmaf(wv.y, av1.z, acc[o][2]);
                    acc[o][3] = fmaf(wv.y, av1.w, acc[o][3]);
                    acc[o][0] = fmaf(wv.z, av2.x, acc[o][0]);
                    acc[o][1] = fmaf(wv.z, av2.y, acc[o][1]);
                    acc[o][2] = fmaf(wv.z, av2.z, acc[o][2]);
                    acc[o][3] = fmaf(wv.z, av2.w, acc[o][3]);
                    acc[o][0] = fmaf(wv.w, av3.x, acc[o][0]);
                    acc[o][1] = fmaf(wv.w, av3.y, acc[o][1]);
                    acc[o][2] = fmaf(wv.w, av3.z, acc[o][2]);
                    acc[o][3] = fmaf(wv.w, av3.w, acc[o][3]);
                }
            }
        }
        if (c + 1 < 13) { cp_wait0(); __syncthreads(); p ^= 1; }
    }

    __syncthreads();   // all reads of h11s/wb done -> safe to alias

    // write conv partials
    if (act) {
        #pragma unroll
        for (int o = 0; o < 4; o++)
            #pragma unroll
            for (int b = 0; b < 4; b++)
                convp[s * 3200 + (cob + o) * 16 + bg * 4 + b] = acc[o][b];
    }

    // residual partials: s=0 -> ci 0..51, s=1 -> ci 52..99
    if (act) {
        #pragma unroll
        for (int o = 0; o < 4; o++)
            #pragma unroll
            for (int b = 0; b < 4; b++) acc[o][b] = 0.f;
        const int ci_lo = s ? 52 : 0;
        const int ci_hi = s ? 100 : 52;
        for (int ci = ci_lo; ci < ci_hi; ci += 4) {
            float4 yv0 = *(const float4*)&yres[(ci + 0) * 16 + bg * 4];
            float4 yv1 = *(const float4*)&yres[(ci + 1) * 16 + bg * 4];
            float4 yv2 = *(const float4*)&yres[(ci + 2) * 16 + bg * 4];
            float4 yv3 = *(const float4*)&yres[(ci + 3) * 16 + bg * 4];
            #pragma unroll
            for (int o = 0; o < 4; o++) {
                float4 wv = __ldg((const float4*)(wd_1 + (cob + o) * 100 + ci));
                acc[o][0] = fmaf(wv.x, yv0.x, acc[o][0]);
                acc[o][1] = fmaf(wv.x, yv0.y, acc[o][1]);
                acc[o][2] = fmaf(wv.x, yv0.z, acc[o][2]);
                acc[o][3] = fmaf(wv.x, yv0.w, acc[o][3]);
                acc[o][0] = fmaf(wv.y, yv1.x, acc[o][0]);
                acc[o][1] = fmaf(wv.y, yv1.y, acc[o][1]);
                acc[o][2] = fmaf(wv.y, yv1.z, acc[o][2]);
                acc[o][3] = fmaf(wv.y, yv1.w, acc[o][3]);
                acc[o][0] = fmaf(wv.z, yv2.x, acc[o][0]);
                acc[o][1] = fmaf(wv.z, yv2.y, acc[o][1]);
                acc[o][2] = fmaf(wv.z, yv2.z, acc[o][2]);
                acc[o][3] = fmaf(wv.z, yv2.w, acc[o][3]);
                acc[o][0] = fmaf(wv.w, yv3.x, acc[o][0]);
                acc[o][1] = fmaf(wv.w, yv3.y, acc[o][1]);
                acc[o][2] = fmaf(wv.w, yv3.z, acc[o][2]);
                acc[o][3] = fmaf(wv.w, yv3.w, acc[o][3]);
            }
        }
        #pragma unroll
        for (int o = 0; o < 4; o++)
            #pragma unroll
            for (int b = 0; b < 4; b++)
                resp[s * 3200 + (cob + o) * 16 + bg * 4 + b] = acc[o][b];
    }
    __syncthreads();

    // combine: conv sum + bias -> inner relu -> + bd + res sum -> outer relu
    for (int i = tid; i < 3200; i += 512) {
        int co = i >> 4, b = i & 15;
        float conv = convp[i] + convp[3200 + i] + __ldg(b2_1 + co);
        float v = fmaxf(conv, 0.f) + __ldg(bd_1 + co) + resp[i] + resp[3200 + i];
        feat[b * 201 + co] = fmaxf(v, 0.f);
    }
    __syncthreads();

    // ------------- head stage A: one thread per (b, c1) output -------------
    for (int o = tid; o < 1600; o += 512) {
        int blx = o & 15, c1 = o >> 4;
        int task = __ldg(task_labels + b0 + blx);
        const float4* W = (const float4*)(hw1 + ((size_t)task * 100 + c1) * 200);
        const float* fr = &feat[blx * 201];
        float a0 = 0.f, a1 = 0.f, a2 = 0.f, a3 = 0.f;
        #pragma unroll 5
        for (int q = 0; q < 50; q++) {
            float4 wv = __ldg(W + q);
            a0 = fmaf(fr[4 * q + 0], wv.x, a0);
            a1 = fmaf(fr[4 * q + 1], wv.y, a1);
            a2 = fmaf(fr[4 * q + 2], wv.z, a2);
            a3 = fmaf(fr[4 * q + 3], wv.w, a3);
        }
        smH[blx * 104 + c1] = tanhf((a0 + a1) + (a2 + a3) + __ldg(hb1 + task * 100 + c1));
    }
    __syncthreads();

    // ------------- head stage B: one thread per batch element -------------
    if (tid < 16) {
        int blx = tid;
        int task = __ldg(task_labels + b0 + blx);
        const float4* W = (const float4*)(hw2 + task * 100);
        const float* hr = &smH[blx * 104];
        float a0 = 0.f, a1 = 0.f, a2 = 0.f, a3 = 0.f;
        #pragma unroll 5
        for (int q = 0; q < 25; q++) {
            float4 wv = __ldg(W + q);
            a0 = fmaf(hr[4 * q + 0], wv.x, a0);
            a1 = fmaf(hr[4 * q + 1], wv.y, a1);
            a2 = fmaf(hr[4 * q + 2], wv.z, a2);
            a3 = fmaf(hr[4 * q + 3], wv.w, a3);
        }
        out[b0 + blx] = (a0 + a1) + (a2 + a3) + __ldg(hb2 + task);
    }
}

// =====================================================================================
extern "C" void kernel_launch(void* const* d_in, const int* in_sizes, int n_in,
                              void* d_out, int out_size)
{
    const float* x    = (const float*)d_in[0];
    const int*   tl   = (const int*)  d_in[1];
    const float* w1_0 = (const float*)d_in[2];
    const float* b1_0 = (const float*)d_in[3];
    const float* w2_0 = (const float*)d_in[4];
    const float* b2_0 = (const float*)d_in[5];
    const float* wd_0 = (const float*)d_in[6];
    const float* bd_0 = (const float*)d_in[7];
    const float* w1_1 = (const float*)d_in[8];
    const float* b1_1 = (const float*)d_in[9];
    const float* w2_1 = (const float*)d_in[10];
    const float* b2_1 = (const float*)d_in[11];
    const float* wd_1 = (const float*)d_in[12];
    const float* bd_1 = (const float*)d_in[13];
    const float* hw1  = (const float*)d_in[14];
    const float* hb1  = (const float*)d_in[15];
    const float* hw2  = (const float*)d_in[16];
    const float* hb2  = (const float*)d_in[17];
    float* out = (float*)d_out;

    const int s1 = 27000 * 4;
    const int s2 = (K2_H + K2_X + 2 * K2_WB) * 4;
    const int s3 = (K3_Y + 2 * K3_WB) * 4;
    const int s4 = (K4_H + K4_YR + K4_FT + K4_HH + 2 * K4_WB) * 4;   // 219,520 B
    cudaFuncSetAttribute(k1, cudaFuncAttributeMaxDynamicSharedMemorySize, s1);
    cudaFuncSetAttribute(k2, cudaFuncAttributeMaxDynamicSharedMemorySize, s2);
    cudaFuncSetAttribute(k3, cudaFuncAttributeMaxDynamicSharedMemorySize, s3);
    cudaFuncSetAttribute(k4, cudaFuncAttributeMaxDynamicSharedMemorySize, s4);

    k1<<<256, 512, s1>>>(x, w1_0, b1_0);
    k2<<<256, 512, s2>>>(x, w2_0, b2_0, wd_0, bd_0);
    k3<<<256, 512, s3>>>(w1_1, b1_1);
    k4<<<256, 512, s4>>>(tl, w2_1, b2_1, wd_1, bd_1, hw1, hb1, hw2, hb2, out);
}

// round 7
// speedup vs baseline: 2.0409x; 1.0218x over previous
#include <cuda_runtime.h>
#include <cstddef>
#include <cstdint>

// ---------------- gmem scratch (layout: [chan][t][batch], batch fastest) ----------------
__device__ float g_h1 [100 * 21 * 4096];
__device__ float g_y  [100 *  9 * 4096];
__device__ float g_h11[200 *  5 * 4096];

// ---------------- helpers ----------------
__device__ __forceinline__ void cp16(float* dst_smem, const float* src) {
    uint32_t s = (uint32_t)__cvta_generic_to_shared(dst_smem);
    asm volatile("cp.async.cg.shared.global [%0], [%1], 16;\n" :: "r"(s), "l"(src));
}
__device__ __forceinline__ void cp_commit() { asm volatile("cp.async.commit_group;\n"); }
__device__ __forceinline__ void cp_wait0()  { asm volatile("cp.async.wait_group 0;\n"); }

// =====================================================================================
// K1: h1[co][t][b] = relu(conv1_0(x)) at t_glob = 235..255 (t=0..20)
// =====================================================================================
__global__ __launch_bounds__(512, 1) void k1(
    const float* __restrict__ x, const float* __restrict__ w1_0, const float* __restrict__ b1_0)
{
    extern __shared__ float sm[];
    float* xs = sm;           // [(ci*25+tau)*16 + bl], 12000
    float* w  = sm + 12000;   // w1_0 full, 15000
    const int tid = threadIdx.x;
    const int b0  = blockIdx.x * 16;

    for (int i = tid; i < 12000; i += 512) {
        int ci = i / 400; int r = i - ci * 400; int bl = r / 25; int tau = r - bl * 25;
        xs[(ci * 25 + tau) * 16 + bl] = x[(size_t)(b0 + bl) * 7680 + ci * 256 + 231 + tau];
    }
    for (int i = tid; i < 15000; i += 512) w[i] = w1_0[i];
    __syncthreads();

    const int bl = tid & 15, cs = tid >> 4;
    for (int m = 0; m < 4; m++) {
        int co = cs + 32 * m;
        if (co >= 100) break;
        float acc[21];
        float bias = __ldg(b1_0 + co);
        #pragma unroll
        for (int t = 0; t < 21; t++) acc[t] = bias;
        for (int ci = 0; ci < 30; ci++) {
            float xw[25];
            const float* xp = &xs[(ci * 25) * 16 + bl];
            #pragma unroll
            for (int tau = 0; tau < 25; tau++) xw[tau] = xp[tau * 16];
            const float* wp = &w[co * 150 + ci * 5];
            #pragma unroll
            for (int k = 0; k < 5; k++) {
                float wv = wp[k];
                #pragma unroll
                for (int t = 0; t < 21; t++) acc[t] = fmaf(xw[t + k], wv, acc[t]);
            }
        }
        #pragma unroll
        for (int t = 0; t < 21; t++)
            g_h1[((size_t)co * 21 + t) * 4096 + b0 + bl] = fmaxf(acc[t], 0.f);
    }
}

// =====================================================================================
// K2: y[co][j][b] = relu(relu(conv2_0(h1)) + bd0 + wd0*x) at t_glob = 239+2j (j=0..8)
// =====================================================================================
#define K2_H  33600
#define K2_X  4320
#define K2_WB 8000
__global__ __launch_bounds__(512, 1) void k2(
    const float* __restrict__ x,
    const float* __restrict__ w2_0, const float* __restrict__ b2_0,
    const float* __restrict__ wd_0, const float* __restrict__ bd_0)
{
    extern __shared__ float sm[];
    float* h1s    = sm;
    float* xs2    = sm + K2_H;
    float* wb[2]  = { sm + K2_H + K2_X, sm + K2_H + K2_X + K2_WB };
    const int tid = threadIdx.x;
    const int b0  = blockIdx.x * 16;
    const int bl  = tid & 15, cs = tid >> 4;

    for (int i = tid; i < 8400; i += 512) {
        int cit = i >> 2, q = i & 3;
        cp16(&h1s[cit * 16 + 4 * q], &g_h1[(size_t)cit * 4096 + b0 + 4 * q]);
    }
    for (int i = tid; i < 2000; i += 512) {
        int co = i / 20, q = i - co * 20;
        cp16(&wb[0][co * 80 + 4 * q], &w2_0[co * 500 + 4 * q]);
    }
    cp_commit();

    for (int i = tid; i < K2_X; i += 512) {
        int ci = i / 144; int r = i - ci * 144; int blx = r / 9; int j = r - blx * 9;
        xs2[(ci * 16 + blx) * 9 + j] = x[(size_t)(b0 + blx) * 7680 + ci * 256 + 239 + 2 * j];
    }

    int cov[4];
    #pragma unroll
    for (int m = 0; m < 4; m++) { int co = cs + 32 * m; cov[m] = (co < 100) ? co : 0; }
    float a[4][9];
    #pragma unroll
    for (int m = 0; m < 4; m++) {
        float bi = __ldg(b2_0 + cov[m]);
        #pragma unroll
        for (int j = 0; j < 9; j++) a[m][j] = bi;
    }

    cp_wait0();
    __syncthreads();

    int p = 0;
    for (int c = 0; c < 7; c++) {
        int ci0 = c * 16;
        int C = (c == 6) ? 4 : 16;
        if (c + 1 < 7) {
            int nci0 = (c + 1) * 16;
            int nC = (c + 1 == 6) ? 4 : 16;
            int per = (5 * nC) >> 2;
            int nw = 100 * per;
            for (int i = tid; i < nw; i += 512) {
                int co = i / per, q = i - co * per;
                cp16(&wb[p ^ 1][co * 80 + 4 * q], &w2_0[co * 500 + nci0 * 5 + 4 * q]);
            }
            cp_commit();
        }
        const float* wB = wb[p];
        for (int cc = 0; cc < C; cc++) {
            float hv[21];
            const float* hp = &h1s[((ci0 + cc) * 21) * 16 + bl];
            #pragma unroll
            for (int t = 0; t < 21; t++) hv[t] = hp[t * 16];
            #pragma unroll
            for (int m = 0; m < 4; m++) {
                const float* wp = &wB[cov[m] * 80 + cc * 5];
                #pragma unroll
                for (int k = 0; k < 5; k++) {
                    float wv = wp[k];
                    #pragma unroll
                    for (int j = 0; j < 9; j++) a[m][j] = fmaf(hv[2 * j + k], wv, a[m][j]);
                }
            }
        }
        if (c + 1 < 7) { cp_wait0(); __syncthreads(); p ^= 1; }
    }

    int nm = (cs < 4) ? 4 : 3;
    for (int m = 0; m < nm; m++) {
        int co = cov[m];
        float r9[9];
        float rb = __ldg(bd_0 + co);
        #pragma unroll
        for (int j = 0; j < 9; j++) r9[j] = fmaxf(a[m][j], 0.f) + rb;   // inner relu
        for (int ci = 0; ci < 30; ci++) {
            float wv = __ldg(wd_0 + co * 30 + ci);
            const float* xp = &xs2[(ci * 16 + bl) * 9];
            #pragma unroll
            for (int j = 0; j < 9; j++) r9[j] = fmaf(xp[j], wv, r9[j]);
        }
        #pragma unroll
        for (int j = 0; j < 9; j++)
            g_y[((size_t)co * 9 + j) * 4096 + b0 + bl] = fmaxf(r9[j], 0.f);
    }
}

// =====================================================================================
// K3: h11[co2][i][b] = relu(conv1_1(y, dil=2)) at t_glob = 247+2i (i=0..4)
// =====================================================================================
#define K3_Y  14400
#define K3_WB 16000
__global__ __launch_bounds__(512, 1) void k3(
    const float* __restrict__ w1_1, const float* __restrict__ b1_1)
{
    extern __shared__ float sm[];
    float* ys    = sm;
    float* wb[2] = { sm + K3_Y, sm + K3_Y + K3_WB };
    const int tid = threadIdx.x;
    const int b0  = blockIdx.x * 16;
    const int bl  = tid & 15, cs = tid >> 4;

    for (int i = tid; i < 3600; i += 512) {
        int cij = i >> 2, q = i & 3;
        cp16(&ys[cij * 16 + 4 * q], &g_y[(size_t)cij * 4096 + b0 + 4 * q]);
    }
    for (int i = tid; i < 4000; i += 512) {
        int co = i / 20, q = i - co * 20;
        cp16(&wb[0][co * 80 + 4 * q], &w1_1[co * 500 + 4 * q]);
    }
    cp_commit();

    int cov[7];
    #pragma unroll
    for (int m = 0; m < 7; m++) { int co = cs + 32 * m; cov[m] = (co < 200) ? co : 0; }
    float a[7][5];
    #pragma unroll
    for (int m = 0; m < 7; m++) {
        float bi = __ldg(b1_1 + cov[m]);
        #pragma unroll
        for (int i = 0; i < 5; i++) a[m][i] = bi;
    }

    cp_wait0();
    __syncthreads();

    int p = 0;
    for (int c = 0; c < 7; c++) {
        int ci0 = c * 16;
        int C = (c == 6) ? 4 : 16;
        if (c + 1 < 7) {
            int nci0 = (c + 1) * 16;
            int nC = (c + 1 == 6) ? 4 : 16;
            int per = (5 * nC) >> 2;
            int nw = 200 * per;
            for (int i = tid; i < nw; i += 512) {
                int co = i / per, q = i - co * per;
                cp16(&wb[p ^ 1][co * 80 + 4 * q], &w1_1[co * 500 + nci0 * 5 + 4 * q]);
            }
            cp_commit();
        }
        const float* wB = wb[p];
        for (int cc = 0; cc < C; cc++) {
            float yv[9];
            const float* yp = &ys[((ci0 + cc) * 9) * 16 + bl];
            #pragma unroll
            for (int j = 0; j < 9; j++) yv[j] = yp[j * 16];
            #pragma unroll
            for (int m = 0; m < 7; m++) {
                const float* wp = &wB[cov[m] * 80 + cc * 5];
                #pragma unroll
                for (int k = 0; k < 5; k++) {
                    float wv = wp[k];
                    #pragma unroll
                    for (int i = 0; i < 5; i++) a[m][i] = fmaf(yv[i + k], wv, a[m][i]);
                }
            }
        }
        if (c + 1 < 7) { cp_wait0(); __syncthreads(); p ^= 1; }
    }

    int nm = (cs < 8) ? 7 : 6;
    for (int m = 0; m < nm; m++) {
        int co2 = cov[m];
        #pragma unroll
        for (int i = 0; i < 5; i++)
            g_h11[((size_t)co2 * 5 + i) * 4096 + b0 + bl] = fmaxf(a[m][i], 0.f);
    }
}

// =====================================================================================
// K4: feat = relu(relu(conv2_1(h11)@t=255) + bd1 + wd1*y[t=255]); fused head.
// No weight smem: each thread streams its 2 weight rows from gmem (L2-resident).
// Thread: cog = tid>>2 (active<100), bg = tid&3; co in {cog, cog+100}; 4 batches.
// smem ~90KB -> 2 CTAs/SM.
// =====================================================================================
#define K4_H    16000               // h11 tile [cik][16b]
#define K4_YR   1600                // yres [ci*16+b]
#define K4_FT   3216                // feat [b*201+co2]
#define K4_HH   1664                // smH  [b*104+c1]
__global__ __launch_bounds__(512, 2) void k4(
    const int* __restrict__ task_labels,
    const float* __restrict__ w2_1, const float* __restrict__ b2_1,
    const float* __restrict__ wd_1, const float* __restrict__ bd_1,
    const float* __restrict__ hw1, const float* __restrict__ hb1,
    const float* __restrict__ hw2, const float* __restrict__ hb2,
    float* __restrict__ out)
{
    extern __shared__ float sm[];
    float* h11s = sm;                          // K4_H
    float* yres = sm + K4_H;                   // K4_YR
    float* feat = sm + K4_H + K4_YR;           // K4_FT
    float* smH  = sm + K4_H + K4_YR + K4_FT;   // K4_HH
    const int tid = threadIdx.x;
    const int b0  = blockIdx.x * 16;

    const int cog = tid >> 2;                  // 0..127, active < 100
    const int bg  = tid & 3;
    const bool act = (cog < 100);
    const int co0 = cog, co1 = cog + 100;

    // stage h11 tile via cp.async
    for (int i = tid; i < 4000; i += 512) {
        int cik = i >> 2, q = i & 3;
        cp16(&h11s[cik * 16 + 4 * q], &g_h11[(size_t)cik * 4096 + b0 + 4 * q]);
    }
    cp_commit();

    // yres: y[:, t=255, batch]
    for (int i = tid; i < K4_YR; i += 512) {
        int blx = i & 15, ci = i >> 4;
        yres[ci * 16 + blx] = g_y[((size_t)ci * 9 + 8) * 4096 + b0 + blx];
    }

    cp_wait0();
    __syncthreads();

    if (act) {
        float acc0[4] = {0.f, 0.f, 0.f, 0.f};
        float acc1[4] = {0.f, 0.f, 0.f, 0.f};
        const float4* W0 = (const float4*)(w2_1 + (size_t)co0 * 1000);
        const float4* W1 = (const float4*)(w2_1 + (size_t)co1 * 1000);
        #pragma unroll 2
        for (int q = 0; q < 250; q++) {
            float4 av0 = *(const float4*)&h11s[(4 * q + 0) * 16 + bg * 4];
            float4 av1 = *(const float4*)&h11s[(4 * q + 1) * 16 + bg * 4];
            float4 av2 = *(const float4*)&h11s[(4 * q + 2) * 16 + bg * 4];
            float4 av3 = *(const float4*)&h11s[(4 * q + 3) * 16 + bg * 4];
            float4 w0 = __ldg(W0 + q);
            float4 w1 = __ldg(W1 + q);
            acc0[0] = fmaf(w0.x, av0.x, acc0[0]);
            acc0[1] = fmaf(w0.x, av0.y, acc0[1]);
            acc0[2] = fmaf(w0.x, av0.z, acc0[2]);
            acc0[3] = fmaf(w0.x, av0.w, acc0[3]);
            acc0[0] = fmaf(w0.y, av1.x, acc0[0]);
            acc0[1] = fmaf(w0.y, av1.y, acc0[1]);
            acc0[2] = fmaf(w0.y, av1.z, acc0[2]);
            acc0[3] = fmaf(w0.y, av1.w, acc0[3]);
            acc0[0] = fmaf(w0.z, av2.x, acc0[0]);
            acc0[1] = fmaf(w0.z, av2.y, acc0[1]);
            acc0[2] = fmaf(w0.z, av2.z, acc0[2]);
            acc0[3] = fmaf(w0.z, av2.w, acc0[3]);
            acc0[0] = fmaf(w0.w, av3.x, acc0[0]);
            acc0[1] = fmaf(w0.w, av3.y, acc0[1]);
            acc0[2] = fmaf(w0.w, av3.z, acc0[2]);
            acc0[3] = fmaf(w0.w, av3.w, acc0[3]);
            acc1[0] = fmaf(w1.x, av0.x, acc1[0]);
            acc1[1] = fmaf(w1.x, av0.y, acc1[1]);
            acc1[2] = fmaf(w1.x, av0.z, acc1[2]);
            acc1[3] = fmaf(w1.x, av0.w, acc1[3]);
            acc1[0] = fmaf(w1.y, av1.x, acc1[0]);
            acc1[1] = fmaf(w1.y, av1.y, acc1[1]);
            acc1[2] = fmaf(w1.y, av1.z, acc1[2]);
            acc1[3] = fmaf(w1.y, av1.w, acc1[3]);
            acc1[0] = fmaf(w1.z, av2.x, acc1[0]);
            acc1[1] = fmaf(w1.z, av2.y, acc1[1]);
            acc1[2] = fmaf(w1.z, av2.z, acc1[2]);
            acc1[3] = fmaf(w1.z, av2.w, acc1[3]);
            acc1[0] = fmaf(w1.w, av3.x, acc1[0]);
            acc1[1] = fmaf(w1.w, av3.y, acc1[1]);
            acc1[2] = fmaf(w1.w, av3.z, acc1[2]);
            acc1[3] = fmaf(w1.w, av3.w, acc1[3]);
        }

        // residual over 100 ci of yres, same tile pattern
        float r0[4] = {0.f, 0.f, 0.f, 0.f};
        float r1[4] = {0.f, 0.f, 0.f, 0.f};
        const float4* D0 = (const float4*)(wd_1 + (size_t)co0 * 100);
        const float4* D1 = (const float4*)(wd_1 + (size_t)co1 * 100);
        #pragma unroll 5
        for (int q = 0; q < 25; q++) {
            float4 yv0 = *(const float4*)&yres[(4 * q + 0) * 16 + bg * 4];
            float4 yv1 = *(const float4*)&yres[(4 * q + 1) * 16 + bg * 4];
            float4 yv2 = *(const float4*)&yres[(4 * q + 2) * 16 + bg * 4];
            float4 yv3 = *(const float4*)&yres[(4 * q + 3) * 16 + bg * 4];
            float4 w0 = __ldg(D0 + q);
            float4 w1 = __ldg(D1 + q);
            r0[0] = fmaf(w0.x, yv0.x, r0[0]);
            r0[1] = fmaf(w0.x, yv0.y, r0[1]);
            r0[2] = fmaf(w0.x, yv0.z, r0[2]);
            r0[3] = fmaf(w0.x, yv0.w, r0[3]);
            r0[0] = fmaf(w0.y, yv1.x, r0[0]);
            r0[1] = fmaf(w0.y, yv1.y, r0[1]);
            r0[2] = fmaf(w0.y, yv1.z, r0[2]);
            r0[3] = fmaf(w0.y, yv1.w, r0[3]);
            r0[0] = fmaf(w0.z, yv2.x, r0[0]);
            r0[1] = fmaf(w0.z, yv2.y, r0[1]);
            r0[2] = fmaf(w0.z, yv2.z, r0[2]);
            r0[3] = fmaf(w0.z, yv2.w, r0[3]);
            r0[0] = fmaf(w0.w, yv3.x, r0[0]);
            r0[1] = fmaf(w0.w, yv3.y, r0[1]);
            r0[2] = fmaf(w0.w, yv3.z, r0[2]);
            r0[3] = fmaf(w0.w, yv3.w, r0[3]);
            r1[0] = fmaf(w1.x, yv0.x, r1[0]);
            r1[1] = fmaf(w1.x, yv0.y, r1[1]);
            r1[2] = fmaf(w1.x, yv0.z, r1[2]);
            r1[3] = fmaf(w1.x, yv0.w, r1[3]);
            r1[0] = fmaf(w1.y, yv1.x, r1[0]);
            r1[1] = fmaf(w1.y, yv1.y, r1[1]);
            r1[2] = fmaf(w1.y, yv1.z, r1[2]);
            r1[3] = fmaf(w1.y, yv1.w, r1[3]);
            r1[0] = fmaf(w1.z, yv2.x, r1[0]);
            r1[1] = fmaf(w1.z, yv2.y, r1[1]);
            r1[2] = fmaf(w1.z, yv2.z, r1[2]);
            r1[3] = fmaf(w1.z, yv2.w, r1[3]);
            r1[0] = fmaf(w1.w, yv3.x, r1[0]);
            r1[1] = fmaf(w1.w, yv3.y, r1[1]);
            r1[2] = fmaf(w1.w, yv3.z, r1[2]);
            r1[3] = fmaf(w1.w, yv3.w, r1[3]);
        }

        // combine: inner relu on conv(+bias), + bd + residual, outer relu
        float b2v0 = __ldg(b2_1 + co0), bdv0 = __ldg(bd_1 + co0);
        float b2v1 = __ldg(b2_1 + co1), bdv1 = __ldg(bd_1 + co1);
        #pragma unroll
        for (int b = 0; b < 4; b++) {
            int blx = bg * 4 + b;
            feat[blx * 201 + co0] = fmaxf(fmaxf(acc0[b] + b2v0, 0.f) + bdv0 + r0[b], 0.f);
            feat[blx * 201 + co1] = fmaxf(fmaxf(acc1[b] + b2v1, 0.f) + bdv1 + r1[b], 0.f);
        }
    }
    __syncthreads();

    // ------------- head stage A: one thread per (b, c1) output -------------
    for (int o = tid; o < 1600; o += 512) {
        int blx = o & 15, c1 = o >> 4;
        int task = __ldg(task_labels + b0 + blx);
        const float4* W = (const float4*)(hw1 + ((size_t)task * 100 + c1) * 200);
        const float* fr = &feat[blx * 201];
        float a0 = 0.f, a1 = 0.f, a2 = 0.f, a3 = 0.f;
        #pragma unroll 5
        for (int q = 0; q < 50; q++) {
            float4 wv = __ldg(W + q);
            a0 = fmaf(fr[4 * q + 0], wv.x, a0);
            a1 = fmaf(fr[4 * q + 1], wv.y, a1);
            a2 = fmaf(fr[4 * q + 2], wv.z, a2);
            a3 = fmaf(fr[4 * q + 3], wv.w, a3);
        }
        smH[blx * 104 + c1] = tanhf((a0 + a1) + (a2 + a3) + __ldg(hb1 + task * 100 + c1));
    }
    __syncthreads();

    // ------------- head stage B: one thread per batch element -------------
    if (tid < 16) {
        int blx = tid;
        int task = __ldg(task_labels + b0 + blx);
        const float4* W = (const float4*)(hw2 + task * 100);
        const float* hr = &smH[blx * 104];
        float a0 = 0.f, a1 = 0.f, a2 = 0.f, a3 = 0.f;
        #pragma unroll 5
        for (int q = 0; q < 25; q++) {
            float4 wv = __ldg(W + q);
            a0 = fmaf(hr[4 * q + 0], wv.x, a0);
            a1 = fmaf(hr[4 * q + 1], wv.y, a1);
            a2 = fmaf(hr[4 * q + 2], wv.z, a2);
            a3 = fmaf(hr[4 * q + 3], wv.w, a3);
        }
        out[b0 + blx] = (a0 + a1) + (a2 + a3) + __ldg(hb2 + task);
    }
}

// =====================================================================================
extern "C" void kernel_launch(void* const* d_in, const int* in_sizes, int n_in,
                              void* d_out, int out_size)
{
    const float* x    = (const float*)d_in[0];
    const int*   tl   = (const int*)  d_in[1];
    const float* w1_0 = (const float*)d_in[2];
    const float* b1_0 = (const float*)d_in[3];
    const float* w2_0 = (const float*)d_in[4];
    const float* b2_0 = (const float*)d_in[5];
    const float* wd_0 = (const float*)d_in[6];
    const float* bd_0 = (const float*)d_in[7];
    const float* w1_1 = (const float*)d_in[8];
    const float* b1_1 = (const float*)d_in[9];
    const float* w2_1 = (const float*)d_in[10];
    const float* b2_1 = (const float*)d_in[11];
    const float* wd_1 = (const float*)d_in[12];
    const float* bd_1 = (const float*)d_in[13];
    const float* hw1  = (const float*)d_in[14];
    const float* hb1  = (const float*)d_in[15];
    const float* hw2  = (const float*)d_in[16];
    const float* hb2  = (const float*)d_in[17];
    float* out = (float*)d_out;

    const int s1 = 27000 * 4;
    const int s2 = (K2_H + K2_X + 2 * K2_WB) * 4;
    const int s3 = (K3_Y + 2 * K3_WB) * 4;
    const int s4 = (K4_H + K4_YR + K4_FT + K4_HH) * 4;   // 89,920 B
    cudaFuncSetAttribute(k1, cudaFuncAttributeMaxDynamicSharedMemorySize, s1);
    cudaFuncSetAttribute(k2, cudaFuncAttributeMaxDynamicSharedMemorySize, s2);
    cudaFuncSetAttribute(k3, cudaFuncAttributeMaxDynamicSharedMemorySize, s3);
    cudaFuncSetAttribute(k4, cudaFuncAttributeMaxDynamicSharedMemorySize, s4);

    k1<<<256, 512, s1>>>(x, w1_0, b1_0);
    k2<<<256, 512, s2>>>(x, w2_0, b2_0, wd_0, bd_0);
    k3<<<256, 512, s3>>>(w1_1, b1_1);
    k4<<<256, 512, s4>>>(tl, w2_1, b2_1, wd_1, bd_1, hw1, hb1, hw2, hb2, out);
}

// round 8
// speedup vs baseline: 2.1953x; 1.0757x over previous
#include <cuda_runtime.h>
#include <cstddef>
#include <cstdint>

// ---------------- gmem scratch ----------------
__device__ float g_h1 [100 * 21 * 4096];
__device__ float g_y  [100 *  9 * 4096];
__device__ float g_h11[200 *  5 * 4096];
// transposed weights (filled by k0 each launch)
__device__ float g_w2T [1000 * 200];   // [cik][co]
__device__ float g_wdT [100 * 200];    // [ci][co]
__device__ float g_hw1T[8 * 200 * 100];// [task][c2][c1]

// ---------------- helpers ----------------
__device__ __forceinline__ void cp16(float* dst_smem, const float* src) {
    uint32_t s = (uint32_t)__cvta_generic_to_shared(dst_smem);
    asm volatile("cp.async.cg.shared.global [%0], [%1], 16;\n" :: "r"(s), "l"(src));
}
__device__ __forceinline__ void cp_commit() { asm volatile("cp.async.commit_group;\n"); }
__device__ __forceinline__ void cp_wait0()  { asm volatile("cp.async.wait_group 0;\n"); }

// =====================================================================================
// K0: weight transposes (runs once per launch, ~1.5MB)
// =====================================================================================
__global__ __launch_bounds__(512, 2) void k0(
    const float* __restrict__ w2_1, const float* __restrict__ wd_1,
    const float* __restrict__ hw1)
{
    const int i = blockIdx.x * blockDim.x + threadIdx.x;
    const int n = blockDim.x * gridDim.x;
    for (int j = i; j < 200000; j += n) {
        int cik = j / 200, co = j - cik * 200;
        g_w2T[j] = __ldg(w2_1 + co * 1000 + cik);
    }
    for (int j = i; j < 20000; j += n) {
        int ci = j / 200, co = j - ci * 200;
        g_wdT[j] = __ldg(wd_1 + co * 100 + ci);
    }
    for (int j = i; j < 160000; j += n) {
        int t = j / 20000; int r = j - t * 20000; int c2 = r / 100; int c1 = r - c2 * 100;
        g_hw1T[j] = __ldg(hw1 + ((size_t)t * 100 + c1) * 200 + c2);
    }
}

// =====================================================================================
// K1: h1[co][t][b] = relu(conv1_0(x)) at t_glob = 235..255 (t=0..20)
// =====================================================================================
__global__ __launch_bounds__(512, 1) void k1(
    const float* __restrict__ x, const float* __restrict__ w1_0, const float* __restrict__ b1_0)
{
    extern __shared__ float sm[];
    float* xs = sm;           // [(ci*25+tau)*16 + bl], 12000
    float* w  = sm + 12000;   // w1_0 full, 15000
    const int tid = threadIdx.x;
    const int b0  = blockIdx.x * 16;

    for (int i = tid; i < 12000; i += 512) {
        int ci = i / 400; int r = i - ci * 400; int bl = r / 25; int tau = r - bl * 25;
        xs[(ci * 25 + tau) * 16 + bl] = x[(size_t)(b0 + bl) * 7680 + ci * 256 + 231 + tau];
    }
    for (int i = tid; i < 15000; i += 512) w[i] = w1_0[i];
    __syncthreads();

    const int bl = tid & 15, cs = tid >> 4;
    for (int m = 0; m < 4; m++) {
        int co = cs + 32 * m;
        if (co >= 100) break;
        float acc[21];
        float bias = __ldg(b1_0 + co);
        #pragma unroll
        for (int t = 0; t < 21; t++) acc[t] = bias;
        for (int ci = 0; ci < 30; ci++) {
            float xw[25];
            const float* xp = &xs[(ci * 25) * 16 + bl];
            #pragma unroll
            for (int tau = 0; tau < 25; tau++) xw[tau] = xp[tau * 16];
            const float* wp = &w[co * 150 + ci * 5];
            #pragma unroll
            for (int k = 0; k < 5; k++) {
                float wv = wp[k];
                #pragma unroll
                for (int t = 0; t < 21; t++) acc[t] = fmaf(xw[t + k], wv, acc[t]);
            }
        }
        #pragma unroll
        for (int t = 0; t < 21; t++)
            g_h1[((size_t)co * 21 + t) * 4096 + b0 + bl] = fmaxf(acc[t], 0.f);
    }
}

// =====================================================================================
// K2: y[co][j][b] = relu(relu(conv2_0(h1)) + bd0 + wd0*x) at t_glob = 239+2j (j=0..8)
// =====================================================================================
#define K2_H  33600
#define K2_X  4320
#define K2_WB 8000
__global__ __launch_bounds__(512, 1) void k2(
    const float* __restrict__ x,
    const float* __restrict__ w2_0, const float* __restrict__ b2_0,
    const float* __restrict__ wd_0, const float* __restrict__ bd_0)
{
    extern __shared__ float sm[];
    float* h1s    = sm;
    float* xs2    = sm + K2_H;
    float* wb[2]  = { sm + K2_H + K2_X, sm + K2_H + K2_X + K2_WB };
    const int tid = threadIdx.x;
    const int b0  = blockIdx.x * 16;
    const int bl  = tid & 15, cs = tid >> 4;

    for (int i = tid; i < 8400; i += 512) {
        int cit = i >> 2, q = i & 3;
        cp16(&h1s[cit * 16 + 4 * q], &g_h1[(size_t)cit * 4096 + b0 + 4 * q]);
    }
    for (int i = tid; i < 2000; i += 512) {
        int co = i / 20, q = i - co * 20;
        cp16(&wb[0][co * 80 + 4 * q], &w2_0[co * 500 + 4 * q]);
    }
    cp_commit();

    for (int i = tid; i < K2_X; i += 512) {
        int ci = i / 144; int r = i - ci * 144; int blx = r / 9; int j = r - blx * 9;
        xs2[(ci * 16 + blx) * 9 + j] = x[(size_t)(b0 + blx) * 7680 + ci * 256 + 239 + 2 * j];
    }

    int cov[4];
    #pragma unroll
    for (int m = 0; m < 4; m++) { int co = cs + 32 * m; cov[m] = (co < 100) ? co : 0; }
    float a[4][9];
    #pragma unroll
    for (int m = 0; m < 4; m++) {
        float bi = __ldg(b2_0 + cov[m]);
        #pragma unroll
        for (int j = 0; j < 9; j++) a[m][j] = bi;
    }

    cp_wait0();
    __syncthreads();

    int p = 0;
    for (int c = 0; c < 7; c++) {
        int ci0 = c * 16;
        int C = (c == 6) ? 4 : 16;
        if (c + 1 < 7) {
            int nci0 = (c + 1) * 16;
            int nC = (c + 1 == 6) ? 4 : 16;
            int per = (5 * nC) >> 2;
            int nw = 100 * per;
            for (int i = tid; i < nw; i += 512) {
                int co = i / per, q = i - co * per;
                cp16(&wb[p ^ 1][co * 80 + 4 * q], &w2_0[co * 500 + nci0 * 5 + 4 * q]);
            }
            cp_commit();
        }
        const float* wB = wb[p];
        for (int cc = 0; cc < C; cc++) {
            float hv[21];
            const float* hp = &h1s[((ci0 + cc) * 21) * 16 + bl];
            #pragma unroll
            for (int t = 0; t < 21; t++) hv[t] = hp[t * 16];
            #pragma unroll
            for (int m = 0; m < 4; m++) {
                const float* wp = &wB[cov[m] * 80 + cc * 5];
                #pragma unroll
                for (int k = 0; k < 5; k++) {
                    float wv = wp[k];
                    #pragma unroll
                    for (int j = 0; j < 9; j++) a[m][j] = fmaf(hv[2 * j + k], wv, a[m][j]);
                }
            }
        }
        if (c + 1 < 7) { cp_wait0(); __syncthreads(); p ^= 1; }
    }

    int nm = (cs < 4) ? 4 : 3;
    for (int m = 0; m < nm; m++) {
        int co = cov[m];
        float r9[9];
        float rb = __ldg(bd_0 + co);
        #pragma unroll
        for (int j = 0; j < 9; j++) r9[j] = fmaxf(a[m][j], 0.f) + rb;   // inner relu
        for (int ci = 0; ci < 30; ci++) {
            float wv = __ldg(wd_0 + co * 30 + ci);
            const float* xp = &xs2[(ci * 16 + bl) * 9];
            #pragma unroll
            for (int j = 0; j < 9; j++) r9[j] = fmaf(xp[j], wv, r9[j]);
        }
        #pragma unroll
        for (int j = 0; j < 9; j++)
            g_y[((size_t)co * 9 + j) * 4096 + b0 + bl] = fmaxf(r9[j], 0.f);
    }
}

// =====================================================================================
// K3: h11[co2][i][b] = relu(conv1_1(y, dil=2)) at t_glob = 247+2i (i=0..4)
// =====================================================================================
#define K3_Y  14400
#define K3_WB 16000
__global__ __launch_bounds__(512, 1) void k3(
    const float* __restrict__ w1_1, const float* __restrict__ b1_1)
{
    extern __shared__ float sm[];
    float* ys    = sm;
    float* wb[2] = { sm + K3_Y, sm + K3_Y + K3_WB };
    const int tid = threadIdx.x;
    const int b0  = blockIdx.x * 16;
    const int bl  = tid & 15, cs = tid >> 4;

    for (int i = tid; i < 3600; i += 512) {
        int cij = i >> 2, q = i & 3;
        cp16(&ys[cij * 16 + 4 * q], &g_y[(size_t)cij * 4096 + b0 + 4 * q]);
    }
    for (int i = tid; i < 4000; i += 512) {
        int co = i / 20, q = i - co * 20;
        cp16(&wb[0][co * 80 + 4 * q], &w1_1[co * 500 + 4 * q]);
    }
    cp_commit();

    int cov[7];
    #pragma unroll
    for (int m = 0; m < 7; m++) { int co = cs + 32 * m; cov[m] = (co < 200) ? co : 0; }
    float a[7][5];
    #pragma unroll
    for (int m = 0; m < 7; m++) {
        float bi = __ldg(b1_1 + cov[m]);
        #pragma unroll
        for (int i = 0; i < 5; i++) a[m][i] = bi;
    }

    cp_wait0();
    __syncthreads();

    int p = 0;
    for (int c = 0; c < 7; c++) {
        int ci0 = c * 16;
        int C = (c == 6) ? 4 : 16;
        if (c + 1 < 7) {
            int nci0 = (c + 1) * 16;
            int nC = (c + 1 == 6) ? 4 : 16;
            int per = (5 * nC) >> 2;
            int nw = 200 * per;
            for (int i = tid; i < nw; i += 512) {
                int co = i / per, q = i - co * per;
                cp16(&wb[p ^ 1][co * 80 + 4 * q], &w1_1[co * 500 + nci0 * 5 + 4 * q]);
            }
            cp_commit();
        }
        const float* wB = wb[p];
        for (int cc = 0; cc < C; cc++) {
            float yv[9];
            const float* yp = &ys[((ci0 + cc) * 9) * 16 + bl];
            #pragma unroll
            for (int j = 0; j < 9; j++) yv[j] = yp[j * 16];
            #pragma unroll
            for (int m = 0; m < 7; m++) {
                const float* wp = &wB[cov[m] * 80 + cc * 5];
                #pragma unroll
                for (int k = 0; k < 5; k++) {
                    float wv = wp[k];
                    #pragma unroll
                    for (int i = 0; i < 5; i++) a[m][i] = fmaf(yv[i + k], wv, a[m][i]);
                }
            }
        }
        if (c + 1 < 7) { cp_wait0(); __syncthreads(); p ^= 1; }
    }

    int nm = (cs < 8) ? 7 : 6;
    for (int m = 0; m < nm; m++) {
        int co2 = cov[m];
        #pragma unroll
        for (int i = 0; i < 5; i++)
            g_h11[((size_t)co2 * 5 + i) * 4096 + b0 + bl] = fmaxf(a[m][i], 0.f);
    }
}

// =====================================================================================
// K4: feat = relu(relu(conv2_1(h11)@t=255) + bd1 + wd1*y[t=255]); fused head.
// Transposed weights: per-iter weight fetch = coalesced float2 (co pair 2cog,2cog+1).
// =====================================================================================
#define K4_H    16000               // h11 tile [cik][16b]
#define K4_YR   1600                // yres [ci*16+b]
#define K4_FT   3216                // feat [b*201+co2]
#define K4_HH   1664                // smH  [b*104+c1]
__global__ __launch_bounds__(512, 2) void k4(
    const int* __restrict__ task_labels,
    const float* __restrict__ b2_1, const float* __restrict__ bd_1,
    const float* __restrict__ hb1,
    const float* __restrict__ hw2, const float* __restrict__ hb2,
    float* __restrict__ out)
{
    extern __shared__ float sm[];
    float* h11s = sm;                          // K4_H
    float* yres = sm + K4_H;                   // K4_YR
    float* feat = sm + K4_H + K4_YR;           // K4_FT
    float* smH  = sm + K4_H + K4_YR + K4_FT;   // K4_HH
    const int tid = threadIdx.x;
    const int b0  = blockIdx.x * 16;

    const int cog = tid >> 2;                  // 0..127, active < 100
    const int bg  = tid & 3;
    const bool act = (cog < 100);
    const int co0 = 2 * cog, co1 = 2 * cog + 1;

    for (int i = tid; i < 4000; i += 512) {
        int cik = i >> 2, q = i & 3;
        cp16(&h11s[cik * 16 + 4 * q], &g_h11[(size_t)cik * 4096 + b0 + 4 * q]);
    }
    cp_commit();

    for (int i = tid; i < K4_YR; i += 512) {
        int blx = i & 15, ci = i >> 4;
        yres[ci * 16 + blx] = g_y[((size_t)ci * 9 + 8) * 4096 + b0 + blx];
    }

    cp_wait0();
    __syncthreads();

    if (act) {
        float acc0[4] = {0.f, 0.f, 0.f, 0.f};
        float acc1[4] = {0.f, 0.f, 0.f, 0.f};
        #pragma unroll 2
        for (int q = 0; q < 250; q++) {
            float4 av0 = *(const float4*)&h11s[(4 * q + 0) * 16 + bg * 4];
            float4 av1 = *(const float4*)&h11s[(4 * q + 1) * 16 + bg * 4];
            float4 av2 = *(const float4*)&h11s[(4 * q + 2) * 16 + bg * 4];
            float4 av3 = *(const float4*)&h11s[(4 * q + 3) * 16 + bg * 4];
            float2 w0 = *(const float2*)&g_w2T[(4 * q + 0) * 200 + co0];
            float2 w1 = *(const float2*)&g_w2T[(4 * q + 1) * 200 + co0];
            float2 w2 = *(const float2*)&g_w2T[(4 * q + 2) * 200 + co0];
            float2 w3 = *(const float2*)&g_w2T[(4 * q + 3) * 200 + co0];
            acc0[0] = fmaf(w0.x, av0.x, acc0[0]);
            acc0[1] = fmaf(w0.x, av0.y, acc0[1]);
            acc0[2] = fmaf(w0.x, av0.z, acc0[2]);
            acc0[3] = fmaf(w0.x, av0.w, acc0[3]);
            acc1[0] = fmaf(w0.y, av0.x, acc1[0]);
            acc1[1] = fmaf(w0.y, av0.y, acc1[1]);
            acc1[2] = fmaf(w0.y, av0.z, acc1[2]);
            acc1[3] = fmaf(w0.y, av0.w, acc1[3]);
            acc0[0] = fmaf(w1.x, av1.x, acc0[0]);
            acc0[1] = fmaf(w1.x, av1.y, acc0[1]);
            acc0[2] = fmaf(w1.x, av1.z, acc0[2]);
            acc0[3] = fmaf(w1.x, av1.w, acc0[3]);
            acc1[0] = fmaf(w1.y, av1.x, acc1[0]);
            acc1[1] = fmaf(w1.y, av1.y, acc1[1]);
            acc1[2] = fmaf(w1.y, av1.z, acc1[2]);
            acc1[3] = fmaf(w1.y, av1.w, acc1[3]);
            acc0[0] = fmaf(w2.x, av2.x, acc0[0]);
            acc0[1] = fmaf(w2.x, av2.y, acc0[1]);
            acc0[2] = fmaf(w2.x, av2.z, acc0[2]);
            acc0[3] = fmaf(w2.x, av2.w, acc0[3]);
            acc1[0] = fmaf(w2.y, av2.x, acc1[0]);
            acc1[1] = fmaf(w2.y, av2.y, acc1[1]);
            acc1[2] = fmaf(w2.y, av2.z, acc1[2]);
            acc1[3] = fmaf(w2.y, av2.w, acc1[3]);
            acc0[0] = fmaf(w3.x, av3.x, acc0[0]);
            acc0[1] = fmaf(w3.x, av3.y, acc0[1]);
            acc0[2] = fmaf(w3.x, av3.z, acc0[2]);
            acc0[3] = fmaf(w3.x, av3.w, acc0[3]);
            acc1[0] = fmaf(w3.y, av3.x, acc1[0]);
            acc1[1] = fmaf(w3.y, av3.y, acc1[1]);
            acc1[2] = fmaf(w3.y, av3.z, acc1[2]);
            acc1[3] = fmaf(w3.y, av3.w, acc1[3]);
        }

        // residual over yres with transposed wd
        float r0[4] = {0.f, 0.f, 0.f, 0.f};
        float r1[4] = {0.f, 0.f, 0.f, 0.f};
        #pragma unroll 5
        for (int q = 0; q < 25; q++) {
            float4 yv0 = *(const float4*)&yres[(4 * q + 0) * 16 + bg * 4];
            float4 yv1 = *(const float4*)&yres[(4 * q + 1) * 16 + bg * 4];
            float4 yv2 = *(const float4*)&yres[(4 * q + 2) * 16 + bg * 4];
            float4 yv3 = *(const float4*)&yres[(4 * q + 3) * 16 + bg * 4];
            float2 w0 = *(const float2*)&g_wdT[(4 * q + 0) * 200 + co0];
            float2 w1 = *(const float2*)&g_wdT[(4 * q + 1) * 200 + co0];
            float2 w2 = *(const float2*)&g_wdT[(4 * q + 2) * 200 + co0];
            float2 w3 = *(const float2*)&g_wdT[(4 * q + 3) * 200 + co0];
            r0[0] = fmaf(w0.x, yv0.x, r0[0]);
            r0[1] = fmaf(w0.x, yv0.y, r0[1]);
            r0[2] = fmaf(w0.x, yv0.z, r0[2]);
            r0[3] = fmaf(w0.x, yv0.w, r0[3]);
            r1[0] = fmaf(w0.y, yv0.x, r1[0]);
            r1[1] = fmaf(w0.y, yv0.y, r1[1]);
            r1[2] = fmaf(w0.y, yv0.z, r1[2]);
            r1[3] = fmaf(w0.y, yv0.w, r1[3]);
            r0[0] = fmaf(w1.x, yv1.x, r0[0]);
            r0[1] = fmaf(w1.x, yv1.y, r0[1]);
            r0[2] = fmaf(w1.x, yv1.z, r0[2]);
            r0[3] = fmaf(w1.x, yv1.w, r0[3]);
            r1[0] = fmaf(w1.y, yv1.x, r1[0]);
            r1[1] = fmaf(w1.y, yv1.y, r1[1]);
            r1[2] = fmaf(w1.y, yv1.z, r1[2]);
            r1[3] = fmaf(w1.y, yv1.w, r1[3]);
            r0[0] = fmaf(w2.x, yv2.x, r0[0]);
            r0[1] = fmaf(w2.x, yv2.y, r0[1]);
            r0[2] = fmaf(w2.x, yv2.z, r0[2]);
            r0[3] = fmaf(w2.x, yv2.w, r0[3]);
            r1[0] = fmaf(w2.y, yv2.x, r1[0]);
            r1[1] = fmaf(w2.y, yv2.y, r1[1]);
            r1[2] = fmaf(w2.y, yv2.z, r1[2]);
            r1[3] = fmaf(w2.y, yv2.w, r1[3]);
            r0[0] = fmaf(w3.x, yv3.x, r0[0]);
            r0[1] = fmaf(w3.x, yv3.y, r0[1]);
            r0[2] = fmaf(w3.x, yv3.z, r0[2]);
            r0[3] = fmaf(w3.x, yv3.w, r0[3]);
            r1[0] = fmaf(w3.y, yv3.x, r1[0]);
            r1[1] = fmaf(w3.y, yv3.y, r1[1]);
            r1[2] = fmaf(w3.y, yv3.z, r1[2]);
            r1[3] = fmaf(w3.y, yv3.w, r1[3]);
        }

        float b2v0 = __ldg(b2_1 + co0), bdv0 = __ldg(bd_1 + co0);
        float b2v1 = __ldg(b2_1 + co1), bdv1 = __ldg(bd_1 + co1);
        #pragma unroll
        for (int b = 0; b < 4; b++) {
            int blx = bg * 4 + b;
            feat[blx * 201 + co0] = fmaxf(fmaxf(acc0[b] + b2v0, 0.f) + bdv0 + r0[b], 0.f);
            feat[blx * 201 + co1] = fmaxf(fmaxf(acc1[b] + b2v1, 0.f) + bdv1 + r1[b], 0.f);
        }
    }
    __syncthreads();

    // ------------- head stage A: thread -> (blx, c1); coalesced hw1T columns -------------
    for (int o = tid; o < 1600; o += 512) {
        int blx = o / 100, c1 = o - blx * 100;
        int task = __ldg(task_labels + b0 + blx);
        const float* Wt = g_hw1T + task * 20000 + c1;
        const float* fr = &feat[blx * 201];
        float a0 = 0.f, a1 = 0.f, a2 = 0.f, a3 = 0.f;
        #pragma unroll 2
        for (int c2 = 0; c2 < 200; c2 += 4) {
            a0 = fmaf(fr[c2 + 0], Wt[(c2 + 0) * 100], a0);
            a1 = fmaf(fr[c2 + 1], Wt[(c2 + 1) * 100], a1);
            a2 = fmaf(fr[c2 + 2], Wt[(c2 + 2) * 100], a2);
            a3 = fmaf(fr[c2 + 3], Wt[(c2 + 3) * 100], a3);
        }
        smH[blx * 104 + c1] = tanhf((a0 + a1) + (a2 + a3) + __ldg(hb1 + task * 100 + c1));
    }
    __syncthreads();

    // ------------- head stage B -------------
    if (tid < 16) {
        int blx = tid;
        int task = __ldg(task_labels + b0 + blx);
        const float4* W = (const float4*)(hw2 + task * 100);
        const float* hr = &smH[blx * 104];
        float a0 = 0.f, a1 = 0.f, a2 = 0.f, a3 = 0.f;
        #pragma unroll 5
        for (int q = 0; q < 25; q++) {
            float4 wv = __ldg(W + q);
            a0 = fmaf(hr[4 * q + 0], wv.x, a0);
            a1 = fmaf(hr[4 * q + 1], wv.y, a1);
            a2 = fmaf(hr[4 * q + 2], wv.z, a2);
            a3 = fmaf(hr[4 * q + 3], wv.w, a3);
        }
        out[b0 + blx] = (a0 + a1) + (a2 + a3) + __ldg(hb2 + task);
    }
}

// =====================================================================================
extern "C" void kernel_launch(void* const* d_in, const int* in_sizes, int n_in,
                              void* d_out, int out_size)
{
    const float* x    = (const float*)d_in[0];
    const int*   tl   = (const int*)  d_in[1];
    const float* w1_0 = (const float*)d_in[2];
    const float* b1_0 = (const float*)d_in[3];
    const float* w2_0 = (const float*)d_in[4];
    const float* b2_0 = (const float*)d_in[5];
    const float* wd_0 = (const float*)d_in[6];
    const float* bd_0 = (const float*)d_in[7];
    const float* w1_1 = (const float*)d_in[8];
    const float* b1_1 = (const float*)d_in[9];
    const float* w2_1 = (const float*)d_in[10];
    const float* b2_1 = (const float*)d_in[11];
    const float* wd_1 = (const float*)d_in[12];
    const float* bd_1 = (const float*)d_in[13];
    const float* hw1  = (const float*)d_in[14];
    const float* hb1  = (const float*)d_in[15];
    const float* hw2  = (const float*)d_in[16];
    const float* hb2  = (const float*)d_in[17];
    float* out = (float*)d_out;

    const int s1 = 27000 * 4;
    const int s2 = (K2_H + K2_X + 2 * K2_WB) * 4;
    const int s3 = (K3_Y + 2 * K3_WB) * 4;
    const int s4 = (K4_H + K4_YR + K4_FT + K4_HH) * 4;   // 89,920 B
    cudaFuncSetAttribute(k1, cudaFuncAttributeMaxDynamicSharedMemorySize, s1);
    cudaFuncSetAttribute(k2, cudaFuncAttributeMaxDynamicSharedMemorySize, s2);
    cudaFuncSetAttribute(k3, cudaFuncAttributeMaxDynamicSharedMemorySize, s3);
    cudaFuncSetAttribute(k4, cudaFuncAttributeMaxDynamicSharedMemorySize, s4);

    k0<<<148, 512>>>(w2_1, wd_1, hw1);
    k1<<<256, 512, s1>>>(x, w1_0, b1_0);
    k2<<<256, 512, s2>>>(x, w2_0, b2_0, wd_0, bd_0);
    k3<<<256, 512, s3>>>(w1_1, b1_1);
    k4<<<256, 512, s4>>>(tl, b2_1, bd_1, hb1, hw2, hb2, out);
}

// round 9
// speedup vs baseline: 2.5093x; 1.1430x over previous
#include <cuda_runtime.h>
#include <cstddef>
#include <cstdint>

// ---------------- gmem scratch ----------------
__device__ float g_h1 [100 * 21 * 4096];
__device__ float g_y  [100 *  9 * 4096];
__device__ float g_h11[200 *  5 * 4096];
// transposed weights (filled by k0 each launch)
__device__ float g_w2T [1000 * 200];    // w2_1: [cik][co]
__device__ float g_wdT [100 * 200];     // wd_1: [ci][co]
__device__ float g_hw1T[8 * 200 * 100]; // hw1:  [task][c2][c1]
__device__ float g_w20T[500 * 100];     // w2_0: [cik][co]
__device__ float g_w11T[500 * 200];     // w1_1: [cik][co]
__device__ float g_wd0T[30 * 100];      // wd_0: [ci][co]

// ---------------- helpers ----------------
__device__ __forceinline__ void cp16(float* dst_smem, const float* src) {
    uint32_t s = (uint32_t)__cvta_generic_to_shared(dst_smem);
    asm volatile("cp.async.cg.shared.global [%0], [%1], 16;\n" :: "r"(s), "l"(src));
}
__device__ __forceinline__ void cp_commit() { asm volatile("cp.async.commit_group;\n"); }
__device__ __forceinline__ void cp_wait0()  { asm volatile("cp.async.wait_group 0;\n"); }
__device__ __forceinline__ void fma4(float4& a, float w, const float4& v) {
    a.x = fmaf(w, v.x, a.x); a.y = fmaf(w, v.y, a.y);
    a.z = fmaf(w, v.z, a.z); a.w = fmaf(w, v.w, a.w);
}

// =====================================================================================
// K0: weight transposes
// =====================================================================================
__global__ __launch_bounds__(512, 2) void k0(
    const float* __restrict__ w2_1, const float* __restrict__ wd_1,
    const float* __restrict__ hw1,  const float* __restrict__ w2_0,
    const float* __restrict__ w1_1, const float* __restrict__ wd_0)
{
    const int i = blockIdx.x * blockDim.x + threadIdx.x;
    const int n = blockDim.x * gridDim.x;
    for (int j = i; j < 200000; j += n) {
        int cik = j / 200, co = j - cik * 200;
        g_w2T[j] = __ldg(w2_1 + co * 1000 + cik);
    }
    for (int j = i; j < 20000; j += n) {
        int ci = j / 200, co = j - ci * 200;
        g_wdT[j] = __ldg(wd_1 + co * 100 + ci);
    }
    for (int j = i; j < 160000; j += n) {
        int t = j / 20000; int r = j - t * 20000; int c2 = r / 100; int c1 = r - c2 * 100;
        g_hw1T[j] = __ldg(hw1 + ((size_t)t * 100 + c1) * 200 + c2);
    }
    for (int j = i; j < 50000; j += n) {
        int cik = j / 100, co = j - cik * 100;
        g_w20T[j] = __ldg(w2_0 + co * 500 + cik);
    }
    for (int j = i; j < 100000; j += n) {
        int cik = j / 200, co = j - cik * 200;
        g_w11T[j] = __ldg(w1_1 + co * 500 + cik);
    }
    for (int j = i; j < 3000; j += n) {
        int ci = j / 100, co = j - ci * 100;
        g_wd0T[j] = __ldg(wd_0 + co * 30 + ci);
    }
}

// =====================================================================================
// K1: h1[co][t][b] = relu(conv1_0(x)) at t_glob = 235..255 (t=0..20)   [unchanged]
// =====================================================================================
__global__ __launch_bounds__(512, 1) void k1(
    const float* __restrict__ x, const float* __restrict__ w1_0, const float* __restrict__ b1_0)
{
    extern __shared__ float sm[];
    float* xs = sm;           // [(ci*25+tau)*16 + bl], 12000
    float* w  = sm + 12000;   // w1_0 full, 15000
    const int tid = threadIdx.x;
    const int b0  = blockIdx.x * 16;

    for (int i = tid; i < 12000; i += 512) {
        int ci = i / 400; int r = i - ci * 400; int bl = r / 25; int tau = r - bl * 25;
        xs[(ci * 25 + tau) * 16 + bl] = x[(size_t)(b0 + bl) * 7680 + ci * 256 + 231 + tau];
    }
    for (int i = tid; i < 15000; i += 512) w[i] = w1_0[i];
    __syncthreads();

    const int bl = tid & 15, cs = tid >> 4;
    for (int m = 0; m < 4; m++) {
        int co = cs + 32 * m;
        if (co >= 100) break;
        float acc[21];
        float bias = __ldg(b1_0 + co);
        #pragma unroll
        for (int t = 0; t < 21; t++) acc[t] = bias;
        for (int ci = 0; ci < 30; ci++) {
            float xw[25];
            const float* xp = &xs[(ci * 25) * 16 + bl];
            #pragma unroll
            for (int tau = 0; tau < 25; tau++) xw[tau] = xp[tau * 16];
            const float* wp = &w[co * 150 + ci * 5];
            #pragma unroll
            for (int k = 0; k < 5; k++) {
                float wv = wp[k];
                #pragma unroll
                for (int t = 0; t < 21; t++) acc[t] = fmaf(xw[t + k], wv, acc[t]);
            }
        }
        #pragma unroll
        for (int t = 0; t < 21; t++)
            g_h1[((size_t)co * 21 + t) * 4096 + b0 + bl] = fmaxf(acc[t], 0.f);
    }
}

// =====================================================================================
// K2: y[co][j][b] = relu(relu(conv2_0(h1)) + bd0 + wd0*x) at t_glob = 239+2j (j=0..8)
// Direct transposed-weight streaming, no chunk barriers. Thread = (co, 4-batch group).
// =====================================================================================
#define K2_H  33600                 // h1 tile [ci][t][16b]
#define K2_X  4320                  // xs2 [(ci*9+j)*16 + bl]
__global__ __launch_bounds__(512, 1) void k2(
    const float* __restrict__ x,
    const float* __restrict__ b2_0, const float* __restrict__ bd_0)
{
    extern __shared__ float sm[];
    float* h1s = sm;
    float* xs2 = sm + K2_H;
    const int tid = threadIdx.x;
    const int b0  = blockIdx.x * 16;

    for (int i = tid; i < 8400; i += 512) {
        int cit = i >> 2, q = i & 3;
        cp16(&h1s[cit * 16 + 4 * q], &g_h1[(size_t)cit * 4096 + b0 + 4 * q]);
    }
    cp_commit();

    // xs2: x at t=239+2j, layout [ci][j][16b]
    for (int i = tid; i < K2_X; i += 512) {
        int ci = i / 144; int r = i - ci * 144; int j = r >> 4; int bl = r & 15;
        xs2[(ci * 9 + j) * 16 + bl] = x[(size_t)(b0 + bl) * 7680 + ci * 256 + 239 + 2 * j];
    }

    cp_wait0();
    __syncthreads();

    const int cog = tid >> 2;          // 0..127, active < 100
    const int bg  = tid & 3;
    if (cog < 100) {
        const int co = cog;
        float4 acc[9];
        {
            float bi = __ldg(b2_0 + co);
            #pragma unroll
            for (int j = 0; j < 9; j++) acc[j] = make_float4(bi, bi, bi, bi);
        }
        for (int ci = 0; ci < 100; ci++) {
            const float* wr = &g_w20T[ci * 500 + co];    // (ci*5+k)*100 + co
            float w0 = wr[0], w1 = wr[100], w2 = wr[200], w3 = wr[300], w4 = wr[400];
            const float* hp = &h1s[(ci * 21) * 16 + bg * 4];
            // sliding window over t = 2j..2j+4
            float4 v0 = *(const float4*)&hp[0 * 16];
            float4 v1 = *(const float4*)&hp[1 * 16];
            float4 v2 = *(const float4*)&hp[2 * 16];
            float4 v3 = *(const float4*)&hp[3 * 16];
            float4 v4 = *(const float4*)&hp[4 * 16];
            #pragma unroll
            for (int j = 0; j < 9; j++) {
                fma4(acc[j], w0, v0);
                fma4(acc[j], w1, v1);
                fma4(acc[j], w2, v2);
                fma4(acc[j], w3, v3);
                fma4(acc[j], w4, v4);
                if (j < 8) {
                    v0 = v2; v1 = v3; v2 = v4;
                    v3 = *(const float4*)&hp[(2 * j + 5) * 16];
                    v4 = *(const float4*)&hp[(2 * j + 6) * 16];
                }
            }
        }
        // inner relu + bd, then residual
        {
            float bd = __ldg(bd_0 + co);
            #pragma unroll
            for (int j = 0; j < 9; j++) {
                acc[j].x = fmaxf(acc[j].x, 0.f) + bd;
                acc[j].y = fmaxf(acc[j].y, 0.f) + bd;
                acc[j].z = fmaxf(acc[j].z, 0.f) + bd;
                acc[j].w = fmaxf(acc[j].w, 0.f) + bd;
            }
        }
        for (int ci = 0; ci < 30; ci++) {
            float wv = g_wd0T[ci * 100 + co];
            const float* xp = &xs2[(ci * 9) * 16 + bg * 4];
            #pragma unroll
            for (int j = 0; j < 9; j++) {
                float4 av = *(const float4*)&xp[j * 16];
                fma4(acc[j], wv, av);
            }
        }
        #pragma unroll
        for (int j = 0; j < 9; j++) {
            float4 r;
            r.x = fmaxf(acc[j].x, 0.f); r.y = fmaxf(acc[j].y, 0.f);
            r.z = fmaxf(acc[j].z, 0.f); r.w = fmaxf(acc[j].w, 0.f);
            *(float4*)&g_y[((size_t)co * 9 + j) * 4096 + b0 + bg * 4] = r;
        }
    }
}

// =====================================================================================
// K3: h11[co2][i][b] = relu(conv1_1(y, dil=2)) at t_glob = 247+2i (i=0..4)
// Direct transposed-weight streaming (float2 per co-pair), 2 CTAs/SM, no chunk barriers.
// =====================================================================================
#define K3_Y  14400                 // y tile [ci][j][16b]
__global__ __launch_bounds__(512, 2) void k3(const float* __restrict__ b1_1)
{
    extern __shared__ float sm[];
    float* ys = sm;
    const int tid = threadIdx.x;
    const int b0  = blockIdx.x * 16;

    for (int i = tid; i < 3600; i += 512) {
        int cij = i >> 2, q = i & 3;
        cp16(&ys[cij * 16 + 4 * q], &g_y[(size_t)cij * 4096 + b0 + 4 * q]);
    }
    cp_commit();
    cp_wait0();
    __syncthreads();

    const int cog = tid >> 2;          // 0..127, active < 100 (co pairs)
    const int bg  = tid & 3;
    if (cog < 100) {
        const int co0 = 2 * cog, co1 = co0 + 1;
        float4 a0[5], a1[5];
        {
            float bi0 = __ldg(b1_1 + co0), bi1 = __ldg(b1_1 + co1);
            #pragma unroll
            for (int i = 0; i < 5; i++) {
                a0[i] = make_float4(bi0, bi0, bi0, bi0);
                a1[i] = make_float4(bi1, bi1, bi1, bi1);
            }
        }
        for (int ci = 0; ci < 100; ci++) {
            const float* yp = &ys[(ci * 9) * 16 + bg * 4];
            #pragma unroll
            for (int k = 0; k < 5; k++) {
                float2 w = *(const float2*)&g_w11T[(ci * 5 + k) * 200 + co0];
                #pragma unroll
                for (int i = 0; i < 5; i++) {
                    float4 av = *(const float4*)&yp[(k + i) * 16];
                    fma4(a0[i], w.x, av);
                    fma4(a1[i], w.y, av);
                }
            }
        }
        #pragma unroll
        for (int i = 0; i < 5; i++) {
            float4 r0, r1;
            r0.x = fmaxf(a0[i].x, 0.f); r0.y = fmaxf(a0[i].y, 0.f);
            r0.z = fmaxf(a0[i].z, 0.f); r0.w = fmaxf(a0[i].w, 0.f);
            r1.x = fmaxf(a1[i].x, 0.f); r1.y = fmaxf(a1[i].y, 0.f);
            r1.z = fmaxf(a1[i].z, 0.f); r1.w = fmaxf(a1[i].w, 0.f);
            *(float4*)&g_h11[((size_t)co0 * 5 + i) * 4096 + b0 + bg * 4] = r0;
            *(float4*)&g_h11[((size_t)co1 * 5 + i) * 4096 + b0 + bg * 4] = r1;
        }
    }
}

// =====================================================================================
// K4: feat = relu(relu(conv2_1(h11)@t=255) + bd1 + wd1*y[t=255]); fused head. [unchanged]
// =====================================================================================
#define K4_H    16000
#define K4_YR   1600
#define K4_FT   3216
#define K4_HH   1664
__global__ __launch_bounds__(512, 2) void k4(
    const int* __restrict__ task_labels,
    const float* __restrict__ b2_1, const float* __restrict__ bd_1,
    const float* __restrict__ hb1,
    const float* __restrict__ hw2, const float* __restrict__ hb2,
    float* __restrict__ out)
{
    extern __shared__ float sm[];
    float* h11s = sm;
    float* yres = sm + K4_H;
    float* feat = sm + K4_H + K4_YR;
    float* smH  = sm + K4_H + K4_YR + K4_FT;
    const int tid = threadIdx.x;
    const int b0  = blockIdx.x * 16;

    const int cog = tid >> 2;
    const int bg  = tid & 3;
    const bool act = (cog < 100);
    const int co0 = 2 * cog, co1 = 2 * cog + 1;

    for (int i = tid; i < 4000; i += 512) {
        int cik = i >> 2, q = i & 3;
        cp16(&h11s[cik * 16 + 4 * q], &g_h11[(size_t)cik * 4096 + b0 + 4 * q]);
    }
    cp_commit();

    for (int i = tid; i < K4_YR; i += 512) {
        int blx = i & 15, ci = i >> 4;
        yres[ci * 16 + blx] = g_y[((size_t)ci * 9 + 8) * 4096 + b0 + blx];
    }

    cp_wait0();
    __syncthreads();

    if (act) {
        float acc0[4] = {0.f, 0.f, 0.f, 0.f};
        float acc1[4] = {0.f, 0.f, 0.f, 0.f};
        #pragma unroll 2
        for (int q = 0; q < 250; q++) {
            float4 av0 = *(const float4*)&h11s[(4 * q + 0) * 16 + bg * 4];
            float4 av1 = *(const float4*)&h11s[(4 * q + 1) * 16 + bg * 4];
            float4 av2 = *(const float4*)&h11s[(4 * q + 2) * 16 + bg * 4];
            float4 av3 = *(const float4*)&h11s[(4 * q + 3) * 16 + bg * 4];
            float2 w0 = *(const float2*)&g_w2T[(4 * q + 0) * 200 + co0];
            float2 w1 = *(const float2*)&g_w2T[(4 * q + 1) * 200 + co0];
            float2 w2 = *(const float2*)&g_w2T[(4 * q + 2) * 200 + co0];
            float2 w3 = *(const float2*)&g_w2T[(4 * q + 3) * 200 + co0];
            acc0[0] = fmaf(w0.x, av0.x, acc0[0]);
            acc0[1] = fmaf(w0.x, av0.y, acc0[1]);
            acc0[2] = fmaf(w0.x, av0.z, acc0[2]);
            acc0[3] = fmaf(w0.x, av0.w, acc0[3]);
            acc1[0] = fmaf(w0.y, av0.x, acc1[0]);
            acc1[1] = fmaf(w0.y, av0.y, acc1[1]);
            acc1[2] = fmaf(w0.y, av0.z, acc1[2]);
            acc1[3] = fmaf(w0.y, av0.w, acc1[3]);
            acc0[0] = fmaf(w1.x, av1.x, acc0[0]);
            acc0[1] = fmaf(w1.x, av1.y, acc0[1]);
            acc0[2] = fmaf(w1.x, av1.z, acc0[2]);
            acc0[3] = fmaf(w1.x, av1.w, acc0[3]);
            acc1[0] = fmaf(w1.y, av1.x, acc1[0]);
            acc1[1] = fmaf(w1.y, av1.y, acc1[1]);
            acc1[2] = fmaf(w1.y, av1.z, acc1[2]);
            acc1[3] = fmaf(w1.y, av1.w, acc1[3]);
            acc0[0] = fmaf(w2.x, av2.x, acc0[0]);
            acc0[1] = fmaf(w2.x, av2.y, acc0[1]);
            acc0[2] = fmaf(w2.x, av2.z, acc0[2]);
            acc0[3] = fmaf(w2.x, av2.w, acc0[3]);
            acc1[0] = fmaf(w2.y, av2.x, acc1[0]);
            acc1[1] = fmaf(w2.y, av2.y, acc1[1]);
            acc1[2] = fmaf(w2.y, av2.z, acc1[2]);
            acc1[3] = fmaf(w2.y, av2.w, acc1[3]);
            acc0[0] = fmaf(w3.x, av3.x, acc0[0]);
            acc0[1] = fmaf(w3.x, av3.y, acc0[1]);
            acc0[2] = fmaf(w3.x, av3.z, acc0[2]);
            acc0[3] = fmaf(w3.x, av3.w, acc0[3]);
            acc1[0] = fmaf(w3.y, av3.x, acc1[0]);
            acc1[1] = fmaf(w3.y, av3.y, acc1[1]);
            acc1[2] = fmaf(w3.y, av3.z, acc1[2]);
            acc1[3] = fmaf(w3.y, av3.w, acc1[3]);
        }

        float r0[4] = {0.f, 0.f, 0.f, 0.f};
        float r1[4] = {0.f, 0.f, 0.f, 0.f};
        #pragma unroll 5
        for (int q = 0; q < 25; q++) {
            float4 yv0 = *(const float4*)&yres[(4 * q + 0) * 16 + bg * 4];
            float4 yv1 = *(const float4*)&yres[(4 * q + 1) * 16 + bg * 4];
            float4 yv2 = *(const float4*)&yres[(4 * q + 2) * 16 + bg * 4];
            float4 yv3 = *(const float4*)&yres[(4 * q + 3) * 16 + bg * 4];
            float2 w0 = *(const float2*)&g_wdT[(4 * q + 0) * 200 + co0];
            float2 w1 = *(const float2*)&g_wdT[(4 * q + 1) * 200 + co0];
            float2 w2 = *(const float2*)&g_wdT[(4 * q + 2) * 200 + co0];
            float2 w3 = *(const float2*)&g_wdT[(4 * q + 3) * 200 + co0];
            r0[0] = fmaf(w0.x, yv0.x, r0[0]);
            r0[1] = fmaf(w0.x, yv0.y, r0[1]);
            r0[2] = fmaf(w0.x, yv0.z, r0[2]);
            r0[3] = fmaf(w0.x, yv0.w, r0[3]);
            r1[0] = fmaf(w0.y, yv0.x, r1[0]);
            r1[1] = fmaf(w0.y, yv0.y, r1[1]);
            r1[2] = fmaf(w0.y, yv0.z, r1[2]);
            r1[3] = fmaf(w0.y, yv0.w, r1[3]);
            r0[0] = fmaf(w1.x, yv1.x, r0[0]);
            r0[1] = fmaf(w1.x, yv1.y, r0[1]);
            r0[2] = fmaf(w1.x, yv1.z, r0[2]);
            r0[3] = fmaf(w1.x, yv1.w, r0[3]);
            r1[0] = fmaf(w1.y, yv1.x, r1[0]);
            r1[1] = fmaf(w1.y, yv1.y, r1[1]);
            r1[2] = fmaf(w1.y, yv1.z, r1[2]);
            r1[3] = fmaf(w1.y, yv1.w, r1[3]);
            r0[0] = fmaf(w2.x, yv2.x, r0[0]);
            r0[1] = fmaf(w2.x, yv2.y, r0[1]);
            r0[2] = fmaf(w2.x, yv2.z, r0[2]);
            r0[3] = fmaf(w2.x, yv2.w, r0[3]);
            r1[0] = fmaf(w2.y, yv2.x, r1[0]);
            r1[1] = fmaf(w2.y, yv2.y, r1[1]);
            r1[2] = fmaf(w2.y, yv2.z, r1[2]);
            r1[3] = fmaf(w2.y, yv2.w, r1[3]);
            r0[0] = fmaf(w3.x, yv3.x, r0[0]);
            r0[1] = fmaf(w3.x, yv3.y, r0[1]);
            r0[2] = fmaf(w3.x, yv3.z, r0[2]);
            r0[3] = fmaf(w3.x, yv3.w, r0[3]);
            r1[0] = fmaf(w3.y, yv3.x, r1[0]);
            r1[1] = fmaf(w3.y, yv3.y, r1[1]);
            r1[2] = fmaf(w3.y, yv3.z, r1[2]);
            r1[3] = fmaf(w3.y, yv3.w, r1[3]);
        }

        float b2v0 = __ldg(b2_1 + co0), bdv0 = __ldg(bd_1 + co0);
        float b2v1 = __ldg(b2_1 + co1), bdv1 = __ldg(bd_1 + co1);
        #pragma unroll
        for (int b = 0; b < 4; b++) {
            int blx = bg * 4 + b;
            feat[blx * 201 + co0] = fmaxf(fmaxf(acc0[b] + b2v0, 0.f) + bdv0 + r0[b], 0.f);
            feat[blx * 201 + co1] = fmaxf(fmaxf(acc1[b] + b2v1, 0.f) + bdv1 + r1[b], 0.f);
        }
    }
    __syncthreads();

    for (int o = tid; o < 1600; o += 512) {
        int blx = o / 100, c1 = o - blx * 100;
        int task = __ldg(task_labels + b0 + blx);
        const float* Wt = g_hw1T + task * 20000 + c1;
        const float* fr = &feat[blx * 201];
        float a0 = 0.f, a1 = 0.f, a2 = 0.f, a3 = 0.f;
        #pragma unroll 2
        for (int c2 = 0; c2 < 200; c2 += 4) {
            a0 = fmaf(fr[c2 + 0], Wt[(c2 + 0) * 100], a0);
            a1 = fmaf(fr[c2 + 1], Wt[(c2 + 1) * 100], a1);
            a2 = fmaf(fr[c2 + 2], Wt[(c2 + 2) * 100], a2);
            a3 = fmaf(fr[c2 + 3], Wt[(c2 + 3) * 100], a3);
        }
        smH[blx * 104 + c1] = tanhf((a0 + a1) + (a2 + a3) + __ldg(hb1 + task * 100 + c1));
    }
    __syncthreads();

    if (tid < 16) {
        int blx = tid;
        int task = __ldg(task_labels + b0 + blx);
        const float4* W = (const float4*)(hw2 + task * 100);
        const float* hr = &smH[blx * 104];
        float a0 = 0.f, a1 = 0.f, a2 = 0.f, a3 = 0.f;
        #pragma unroll 5
        for (int q = 0; q < 25; q++) {
            float4 wv = __ldg(W + q);
            a0 = fmaf(hr[4 * q + 0], wv.x, a0);
            a1 = fmaf(hr[4 * q + 1], wv.y, a1);
            a2 = fmaf(hr[4 * q + 2], wv.z, a2);
            a3 = fmaf(hr[4 * q + 3], wv.w, a3);
        }
        out[b0 + blx] = (a0 + a1) + (a2 + a3) + __ldg(hb2 + task);
    }
}

// =====================================================================================
extern "C" void kernel_launch(void* const* d_in, const int* in_sizes, int n_in,
                              void* d_out, int out_size)
{
    const float* x    = (const float*)d_in[0];
    const int*   tl   = (const int*)  d_in[1];
    const float* w1_0 = (const float*)d_in[2];
    const float* b1_0 = (const float*)d_in[3];
    const float* w2_0 = (const float*)d_in[4];
    const float* b2_0 = (const float*)d_in[5];
    const float* wd_0 = (const float*)d_in[6];
    const float* bd_0 = (const float*)d_in[7];
    const float* w1_1 = (const float*)d_in[8];
    const float* b1_1 = (const float*)d_in[9];
    const float* w2_1 = (const float*)d_in[10];
    const float* b2_1 = (const float*)d_in[11];
    const float* wd_1 = (const float*)d_in[12];
    const float* bd_1 = (const float*)d_in[13];
    const float* hw1  = (const float*)d_in[14];
    const float* hb1  = (const float*)d_in[15];
    const float* hw2  = (const float*)d_in[16];
    const float* hb2  = (const float*)d_in[17];
    float* out = (float*)d_out;

    const int s1 = 27000 * 4;
    const int s2 = (K2_H + K2_X) * 4;                    // 151,680 B
    const int s3 = K3_Y * 4;                             //  57,600 B
    const int s4 = (K4_H + K4_YR + K4_FT + K4_HH) * 4;   //  89,920 B
    cudaFuncSetAttribute(k1, cudaFuncAttributeMaxDynamicSharedMemorySize, s1);
    cudaFuncSetAttribute(k2, cudaFuncAttributeMaxDynamicSharedMemorySize, s2);
    cudaFuncSetAttribute(k3, cudaFuncAttributeMaxDynamicSharedMemorySize, s3);
    cudaFuncSetAttribute(k4, cudaFuncAttributeMaxDynamicSharedMemorySize, s4);

    k0<<<148, 512>>>(w2_1, wd_1, hw1, w2_0, w1_1, wd_0);
    k1<<<256, 512, s1>>>(x, w1_0, b1_0);
    k2<<<256, 512, s2>>>(x, b2_0, bd_0);
    k3<<<256, 512, s3>>>(b1_1);
    k4<<<256, 512, s4>>>(tl, b2_1, bd_1, hb1, hw2, hb2, out);
}

// round 10
// speedup vs baseline: 2.7106x; 1.0803x over previous
#include <cuda_runtime.h>
#include <cstddef>
#include <cstdint>

typedef unsigned long long ull;

// ---------------- gmem scratch ----------------
__device__ float g_h1 [100 * 21 * 4096];
__device__ float g_y  [100 *  9 * 4096];
__device__ float g_h11[200 *  5 * 4096];
// transposed weights (filled by k0 each launch)
__device__ float g_w2T [1000 * 200];    // w2_1: [cik][co]
__device__ float g_wdT [100 * 200];     // wd_1: [ci][co]
__device__ float g_hw1T[8 * 200 * 100]; // hw1:  [task][c2][c1]
__device__ float g_w20T[500 * 100];     // w2_0: [cik][co]
__device__ float g_w11T[500 * 200];     // w1_1: [cik][co]
__device__ float g_wd0T[30 * 100];      // wd_0: [ci][co]

// ---------------- helpers ----------------
__device__ __forceinline__ void cp16(float* dst_smem, const float* src) {
    uint32_t s = (uint32_t)__cvta_generic_to_shared(dst_smem);
    asm volatile("cp.async.cg.shared.global [%0], [%1], 16;\n" :: "r"(s), "l"(src));
}
__device__ __forceinline__ void cp_commit() { asm volatile("cp.async.commit_group;\n"); }
__device__ __forceinline__ void cp_wait0()  { asm volatile("cp.async.wait_group 0;\n"); }

__device__ __forceinline__ ull pack2(float x, float y) {
    ull r; asm("mov.b64 %0, {%1, %2};" : "=l"(r) : "f"(x), "f"(y)); return r;
}
__device__ __forceinline__ ull bcast2(float x) { return pack2(x, x); }
__device__ __forceinline__ float2 unpack2(ull v) {
    float2 f; asm("mov.b64 {%0, %1}, %2;" : "=f"(f.x), "=f"(f.y) : "l"(v)); return f;
}
__device__ __forceinline__ void fma2(ull& d, ull a, ull b) {
    asm("fma.rn.f32x2 %0, %1, %2, %3;" : "=l"(d) : "l"(a), "l"(b), "l"(d));
}

// =====================================================================================
// K0: weight transposes
// =====================================================================================
__global__ __launch_bounds__(512, 2) void k0(
    const float* __restrict__ w2_1, const float* __restrict__ wd_1,
    const float* __restrict__ hw1,  const float* __restrict__ w2_0,
    const float* __restrict__ w1_1, const float* __restrict__ wd_0)
{
    const int i = blockIdx.x * blockDim.x + threadIdx.x;
    const int n = blockDim.x * gridDim.x;
    for (int j = i; j < 200000; j += n) {
        int cik = j / 200, co = j - cik * 200;
        g_w2T[j] = __ldg(w2_1 + co * 1000 + cik);
    }
    for (int j = i; j < 20000; j += n) {
        int ci = j / 200, co = j - ci * 200;
        g_wdT[j] = __ldg(wd_1 + co * 100 + ci);
    }
    for (int j = i; j < 160000; j += n) {
        int t = j / 20000; int r = j - t * 20000; int c2 = r / 100; int c1 = r - c2 * 100;
        g_hw1T[j] = __ldg(hw1 + ((size_t)t * 100 + c1) * 200 + c2);
    }
    for (int j = i; j < 50000; j += n) {
        int cik = j / 100, co = j - cik * 100;
        g_w20T[j] = __ldg(w2_0 + co * 500 + cik);
    }
    for (int j = i; j < 100000; j += n) {
        int cik = j / 200, co = j - cik * 200;
        g_w11T[j] = __ldg(w1_1 + co * 500 + cik);
    }
    for (int j = i; j < 3000; j += n) {
        int ci = j / 100, co = j - ci * 100;
        g_wd0T[j] = __ldg(wd_0 + co * 30 + ci);
    }
}

// =====================================================================================
// K1: h1[co][t][b] = relu(conv1_0(x)) at t_glob = 235..255 (t=0..20)   [unchanged]
// =====================================================================================
__global__ __launch_bounds__(512, 1) void k1(
    const float* __restrict__ x, const float* __restrict__ w1_0, const float* __restrict__ b1_0)
{
    extern __shared__ float sm[];
    float* xs = sm;           // [(ci*25+tau)*16 + bl], 12000
    float* w  = sm + 12000;   // w1_0 full, 15000
    const int tid = threadIdx.x;
    const int b0  = blockIdx.x * 16;

    for (int i = tid; i < 12000; i += 512) {
        int ci = i / 400; int r = i - ci * 400; int bl = r / 25; int tau = r - bl * 25;
        xs[(ci * 25 + tau) * 16 + bl] = x[(size_t)(b0 + bl) * 7680 + ci * 256 + 231 + tau];
    }
    for (int i = tid; i < 15000; i += 512) w[i] = w1_0[i];
    __syncthreads();

    const int bl = tid & 15, cs = tid >> 4;
    for (int m = 0; m < 4; m++) {
        int co = cs + 32 * m;
        if (co >= 100) break;
        float acc[21];
        float bias = __ldg(b1_0 + co);
        #pragma unroll
        for (int t = 0; t < 21; t++) acc[t] = bias;
        for (int ci = 0; ci < 30; ci++) {
            float xw[25];
            const float* xp = &xs[(ci * 25) * 16 + bl];
            #pragma unroll
            for (int tau = 0; tau < 25; tau++) xw[tau] = xp[tau * 16];
            const float* wp = &w[co * 150 + ci * 5];
            #pragma unroll
            for (int k = 0; k < 5; k++) {
                float wv = wp[k];
                #pragma unroll
                for (int t = 0; t < 21; t++) acc[t] = fmaf(xw[t + k], wv, acc[t]);
            }
        }
        #pragma unroll
        for (int t = 0; t < 21; t++)
            g_h1[((size_t)co * 21 + t) * 4096 + b0 + bl] = fmaxf(acc[t], 0.f);
    }
}

// =====================================================================================
// K2: y = relu(relu(conv2_0(h1)) + bd0 + wd0*x) at 9 pts.  f32x2 packed.
// Thread = (co-pair cop<50, batch-pair bgp 0..7). 1 CTA/SM (152KB smem).
// =====================================================================================
#define K2_H  33600                 // h1 tile [ci][t][16b]
#define K2_X  4320                  // xs2 [(ci*9+j)*16 + bl]
__global__ __launch_bounds__(512, 1) void k2(
    const float* __restrict__ x,
    const float* __restrict__ b2_0, const float* __restrict__ bd_0)
{
    extern __shared__ float sm[];
    float* h1s = sm;
    float* xs2 = sm + K2_H;
    const int tid = threadIdx.x;
    const int b0  = blockIdx.x * 16;

    for (int i = tid; i < 8400; i += 512) {
        int cit = i >> 2, q = i & 3;
        cp16(&h1s[cit * 16 + 4 * q], &g_h1[(size_t)cit * 4096 + b0 + 4 * q]);
    }
    cp_commit();

    for (int i = tid; i < K2_X; i += 512) {
        int ci = i / 144; int r = i - ci * 144; int j = r >> 4; int bl = r & 15;
        xs2[(ci * 9 + j) * 16 + bl] = x[(size_t)(b0 + bl) * 7680 + ci * 256 + 239 + 2 * j];
    }

    cp_wait0();
    __syncthreads();

    const int cop = tid >> 3;          // 0..63, active < 50
    const int bgp = tid & 7;           // batch pair
    if (cop < 50) {
        const int co0 = 2 * cop, co1 = co0 + 1;
        ull a[2][9];
        {
            ull b0v = bcast2(__ldg(b2_0 + co0));
            ull b1v = bcast2(__ldg(b2_0 + co1));
            #pragma unroll
            for (int j = 0; j < 9; j++) { a[0][j] = b0v; a[1][j] = b1v; }
        }
        for (int ci = 0; ci < 100; ci++) {
            const float* hp = &h1s[(ci * 21) * 16 + bgp * 2];
            ull v[21];
            #pragma unroll
            for (int t = 0; t < 21; t++) v[t] = *(const ull*)&hp[t * 16];
            #pragma unroll
            for (int k = 0; k < 5; k++) {
                float2 w = *(const float2*)&g_w20T[(ci * 5 + k) * 100 + co0];
                ull wx = bcast2(w.x), wy = bcast2(w.y);
                #pragma unroll
                for (int j = 0; j < 9; j++) {
                    fma2(a[0][j], wx, v[2 * j + k]);
                    fma2(a[1][j], wy, v[2 * j + k]);
                }
            }
        }
        // inner relu + bd (unpack, relu, repack)
        {
            float bd0v = __ldg(bd_0 + co0), bd1v = __ldg(bd_0 + co1);
            #pragma unroll
            for (int j = 0; j < 9; j++) {
                float2 f0 = unpack2(a[0][j]);
                float2 f1 = unpack2(a[1][j]);
                a[0][j] = pack2(fmaxf(f0.x, 0.f) + bd0v, fmaxf(f0.y, 0.f) + bd0v);
                a[1][j] = pack2(fmaxf(f1.x, 0.f) + bd1v, fmaxf(f1.y, 0.f) + bd1v);
            }
        }
        // residual (packed)
        for (int ci = 0; ci < 30; ci++) {
            float2 w = *(const float2*)&g_wd0T[ci * 100 + co0];
            ull wx = bcast2(w.x), wy = bcast2(w.y);
            const float* xp = &xs2[(ci * 9) * 16 + bgp * 2];
            #pragma unroll
            for (int j = 0; j < 9; j++) {
                ull xv = *(const ull*)&xp[j * 16];
                fma2(a[0][j], wx, xv);
                fma2(a[1][j], wy, xv);
            }
        }
        #pragma unroll
        for (int j = 0; j < 9; j++) {
            float2 f0 = unpack2(a[0][j]);
            float2 f1 = unpack2(a[1][j]);
            f0.x = fmaxf(f0.x, 0.f); f0.y = fmaxf(f0.y, 0.f);
            f1.x = fmaxf(f1.x, 0.f); f1.y = fmaxf(f1.y, 0.f);
            *(float2*)&g_y[((size_t)co0 * 9 + j) * 4096 + b0 + bgp * 2] = f0;
            *(float2*)&g_y[((size_t)co1 * 9 + j) * 4096 + b0 + bgp * 2] = f1;
        }
    }
}

// =====================================================================================
// K3: h11 = relu(conv1_1(y, dil=2)) at 5 pts.  f32x2 packed.
// Thread = (co-quad coq<50, batch-pair bgp 0..7). 2 CTAs/SM.
// =====================================================================================
#define K3_Y  14400                 // y tile [ci][j][16b]
__global__ __launch_bounds__(512, 2) void k3(const float* __restrict__ b1_1)
{
    extern __shared__ float sm[];
    float* ys = sm;
    const int tid = threadIdx.x;
    const int b0  = blockIdx.x * 16;

    for (int i = tid; i < 3600; i += 512) {
        int cij = i >> 2, q = i & 3;
        cp16(&ys[cij * 16 + 4 * q], &g_y[(size_t)cij * 4096 + b0 + 4 * q]);
    }
    cp_commit();
    cp_wait0();
    __syncthreads();

    const int coq = tid >> 3;          // 0..63, active < 50
    const int bgp = tid & 7;
    if (coq < 50) {
        const int co4 = coq * 4;
        ull a[4][5];
        #pragma unroll
        for (int c = 0; c < 4; c++) {
            ull bv = bcast2(__ldg(b1_1 + co4 + c));
            #pragma unroll
            for (int i = 0; i < 5; i++) a[c][i] = bv;
        }
        for (int ci = 0; ci < 100; ci++) {
            const float* yp = &ys[(ci * 9) * 16 + bgp * 2];
            ull v[9];
            #pragma unroll
            for (int j = 0; j < 9; j++) v[j] = *(const ull*)&yp[j * 16];
            #pragma unroll
            for (int k = 0; k < 5; k++) {
                float4 w = *(const float4*)&g_w11T[(ci * 5 + k) * 200 + co4];
                ull w0 = bcast2(w.x), w1 = bcast2(w.y), w2 = bcast2(w.z), w3 = bcast2(w.w);
                #pragma unroll
                for (int i = 0; i < 5; i++) {
                    fma2(a[0][i], w0, v[k + i]);
                    fma2(a[1][i], w1, v[k + i]);
                    fma2(a[2][i], w2, v[k + i]);
                    fma2(a[3][i], w3, v[k + i]);
                }
            }
        }
        #pragma unroll
        for (int c = 0; c < 4; c++)
            #pragma unroll
            for (int i = 0; i < 5; i++) {
                float2 f = unpack2(a[c][i]);
                f.x = fmaxf(f.x, 0.f); f.y = fmaxf(f.y, 0.f);
                *(float2*)&g_h11[((size_t)(co4 + c) * 5 + i) * 4096 + b0 + bgp * 2] = f;
            }
    }
}

// =====================================================================================
// K4: feat = relu(relu(conv2_1(h11)@t=255) + bd1 + wd1*y[t=255]); fused head. f32x2.
// =====================================================================================
#define K4_H    16000
#define K4_YR   1600
#define K4_FT   3216
#define K4_HH   1664
__global__ __launch_bounds__(512, 2) void k4(
    const int* __restrict__ task_labels,
    const float* __restrict__ b2_1, const float* __restrict__ bd_1,
    const float* __restrict__ hb1,
    const float* __restrict__ hw2, const float* __restrict__ hb2,
    float* __restrict__ out)
{
    extern __shared__ float sm[];
    float* h11s = sm;
    float* yres = sm + K4_H;
    float* feat = sm + K4_H + K4_YR;
    float* smH  = sm + K4_H + K4_YR + K4_FT;
    const int tid = threadIdx.x;
    const int b0  = blockIdx.x * 16;

    const int cog = tid >> 2;          // 0..127, active < 100
    const int bg  = tid & 3;
    const bool act = (cog < 100);
    const int co0 = 2 * cog, co1 = 2 * cog + 1;

    for (int i = tid; i < 4000; i += 512) {
        int cik = i >> 2, q = i & 3;
        cp16(&h11s[cik * 16 + 4 * q], &g_h11[(size_t)cik * 4096 + b0 + 4 * q]);
    }
    cp_commit();

    for (int i = tid; i < K4_YR; i += 512) {
        int blx = i & 15, ci = i >> 4;
        yres[ci * 16 + blx] = g_y[((size_t)ci * 9 + 8) * 4096 + b0 + blx];
    }

    cp_wait0();
    __syncthreads();

    if (act) {
        ull c0l = 0, c0h = 0, c1l = 0, c1h = 0;
        #pragma unroll 2
        for (int q = 0; q < 250; q++) {
            ulonglong2 av0 = *(const ulonglong2*)&h11s[(4 * q + 0) * 16 + bg * 4];
            ulonglong2 av1 = *(const ulonglong2*)&h11s[(4 * q + 1) * 16 + bg * 4];
            ulonglong2 av2 = *(const ulonglong2*)&h11s[(4 * q + 2) * 16 + bg * 4];
            ulonglong2 av3 = *(const ulonglong2*)&h11s[(4 * q + 3) * 16 + bg * 4];
            float2 w0 = *(const float2*)&g_w2T[(4 * q + 0) * 200 + co0];
            float2 w1 = *(const float2*)&g_w2T[(4 * q + 1) * 200 + co0];
            float2 w2 = *(const float2*)&g_w2T[(4 * q + 2) * 200 + co0];
            float2 w3 = *(const float2*)&g_w2T[(4 * q + 3) * 200 + co0];
            ull w0x = bcast2(w0.x), w0y = bcast2(w0.y);
            ull w1x = bcast2(w1.x), w1y = bcast2(w1.y);
            ull w2x = bcast2(w2.x), w2y = bcast2(w2.y);
            ull w3x = bcast2(w3.x), w3y = bcast2(w3.y);
            fma2(c0l, w0x, av0.x); fma2(c0h, w0x, av0.y);
            fma2(c1l, w0y, av0.x); fma2(c1h, w0y, av0.y);
            fma2(c0l, w1x, av1.x); fma2(c0h, w1x, av1.y);
            fma2(c1l, w1y, av1.x); fma2(c1h, w1y, av1.y);
            fma2(c0l, w2x, av2.x); fma2(c0h, w2x, av2.y);
            fma2(c1l, w2y, av2.x); fma2(c1h, w2y, av2.y);
            fma2(c0l, w3x, av3.x); fma2(c0h, w3x, av3.y);
            fma2(c1l, w3y, av3.x); fma2(c1h, w3y, av3.y);
        }

        ull r0l = 0, r0h = 0, r1l = 0, r1h = 0;
        #pragma unroll 5
        for (int q = 0; q < 25; q++) {
            ulonglong2 yv0 = *(const ulonglong2*)&yres[(4 * q + 0) * 16 + bg * 4];
            ulonglong2 yv1 = *(const ulonglong2*)&yres[(4 * q + 1) * 16 + bg * 4];
            ulonglong2 yv2 = *(const ulonglong2*)&yres[(4 * q + 2) * 16 + bg * 4];
            ulonglong2 yv3 = *(const ulonglong2*)&yres[(4 * q + 3) * 16 + bg * 4];
            float2 w0 = *(const float2*)&g_wdT[(4 * q + 0) * 200 + co0];
            float2 w1 = *(const float2*)&g_wdT[(4 * q + 1) * 200 + co0];
            float2 w2 = *(const float2*)&g_wdT[(4 * q + 2) * 200 + co0];
            float2 w3 = *(const float2*)&g_wdT[(4 * q + 3) * 200 + co0];
            ull w0x = bcast2(w0.x), w0y = bcast2(w0.y);
            ull w1x = bcast2(w1.x), w1y = bcast2(w1.y);
            ull w2x = bcast2(w2.x), w2y = bcast2(w2.y);
            ull w3x = bcast2(w3.x), w3y = bcast2(w3.y);
            fma2(r0l, w0x, yv0.x); fma2(r0h, w0x, yv0.y);
            fma2(r1l, w0y, yv0.x); fma2(r1h, w0y, yv0.y);
            fma2(r0l, w1x, yv1.x); fma2(r0h, w1x, yv1.y);
            fma2(r1l, w1y, yv1.x); fma2(r1h, w1y, yv1.y);
            fma2(r0l, w2x, yv2.x); fma2(r0h, w2x, yv2.y);
            fma2(r1l, w2y, yv2.x); fma2(r1h, w2y, yv2.y);
            fma2(r0l, w3x, yv3.x); fma2(r0h, w3x, yv3.y);
            fma2(r1l, w3y, yv3.x); fma2(r1h, w3y, yv3.y);
        }

        float b2v0 = __ldg(b2_1 + co0), bdv0 = __ldg(bd_1 + co0);
        float b2v1 = __ldg(b2_1 + co1), bdv1 = __ldg(bd_1 + co1);
        float2 cl0 = unpack2(c0l), ch0 = unpack2(c0h);
        float2 cl1 = unpack2(c1l), ch1 = unpack2(c1h);
        float2 sl0 = unpack2(r0l), sh0 = unpack2(r0h);
        float2 sl1 = unpack2(r1l), sh1 = unpack2(r1h);
        float conv0[4] = { cl0.x, cl0.y, ch0.x, ch0.y };
        float conv1[4] = { cl1.x, cl1.y, ch1.x, ch1.y };
        float res0[4]  = { sl0.x, sl0.y, sh0.x, sh0.y };
        float res1[4]  = { sl1.x, sl1.y, sh1.x, sh1.y };
        #pragma unroll
        for (int b = 0; b < 4; b++) {
            int blx = bg * 4 + b;
            feat[blx * 201 + co0] = fmaxf(fmaxf(conv0[b] + b2v0, 0.f) + bdv0 + res0[b], 0.f);
            feat[blx * 201 + co1] = fmaxf(fmaxf(conv1[b] + b2v1, 0.f) + bdv1 + res1[b], 0.f);
        }
    }
    __syncthreads();

    // ------------- head stage A: thread -> (blx, c1-pair); packed fma -------------
    for (int o = tid; o < 800; o += 512) {
        int blx = o / 50, c1p = o - blx * 50;
        int task = __ldg(task_labels + b0 + blx);
        const float* Wt = g_hw1T + task * 20000 + c1p * 2;
        const float* fr = &feat[blx * 201];
        ull acc = 0;
        #pragma unroll 4
        for (int c2 = 0; c2 < 200; c2++) {
            float2 w = *(const float2*)&Wt[c2 * 100];
            ull wp; asm("mov.b64 %0, {%1, %2};" : "=l"(wp) : "f"(w.x), "f"(w.y));
            fma2(acc, bcast2(fr[c2]), wp);
        }
        float2 s = unpack2(acc);
        float2 hb = *(const float2*)&hb1[task * 100 + c1p * 2];
        smH[blx * 104 + c1p * 2 + 0] = tanhf(s.x + hb.x);
        smH[blx * 104 + c1p * 2 + 1] = tanhf(s.y + hb.y);
    }
    __syncthreads();

    // ------------- head stage B -------------
    if (tid < 16) {
        int blx = tid;
        int task = __ldg(task_labels + b0 + blx);
        const float4* W = (const float4*)(hw2 + task * 100);
        const float* hr = &smH[blx * 104];
        float a0 = 0.f, a1 = 0.f, a2 = 0.f, a3 = 0.f;
        #pragma unroll 5
        for (int q = 0; q < 25; q++) {
            float4 wv = __ldg(W + q);
            a0 = fmaf(hr[4 * q + 0], wv.x, a0);
            a1 = fmaf(hr[4 * q + 1], wv.y, a1);
            a2 = fmaf(hr[4 * q + 2], wv.z, a2);
            a3 = fmaf(hr[4 * q + 3], wv.w, a3);
        }
        out[b0 + blx] = (a0 + a1) + (a2 + a3) + __ldg(hb2 + task);
    }
}

// =====================================================================================
extern "C" void kernel_launch(void* const* d_in, const int* in_sizes, int n_in,
                              void* d_out, int out_size)
{
    const float* x    = (const float*)d_in[0];
    const int*   tl   = (const int*)  d_in[1];
    const float* w1_0 = (const float*)d_in[2];
    const float* b1_0 = (const float*)d_in[3];
    const float* w2_0 = (const float*)d_in[4];
    const float* b2_0 = (const float*)d_in[5];
    const float* wd_0 = (const float*)d_in[6];
    const float* bd_0 = (const float*)d_in[7];
    const float* w1_1 = (const float*)d_in[8];
    const float* b1_1 = (const float*)d_in[9];
    const float* w2_1 = (const float*)d_in[10];
    const float* b2_1 = (const float*)d_in[11];
    const float* wd_1 = (const float*)d_in[12];
    const float* bd_1 = (const float*)d_in[13];
    const float* hw1  = (const float*)d_in[14];
    const float* hb1  = (const float*)d_in[15];
    const float* hw2  = (const float*)d_in[16];
    const float* hb2  = (const float*)d_in[17];
    float* out = (float*)d_out;

    const int s1 = 27000 * 4;
    const int s2 = (K2_H + K2_X) * 4;
    const int s3 = K3_Y * 4;
    const int s4 = (K4_H + K4_YR + K4_FT + K4_HH) * 4;
    cudaFuncSetAttribute(k1, cudaFuncAttributeMaxDynamicSharedMemorySize, s1);
    cudaFuncSetAttribute(k2, cudaFuncAttributeMaxDynamicSharedMemorySize, s2);
    cudaFuncSetAttribute(k3, cudaFuncAttributeMaxDynamicSharedMemorySize, s3);
    cudaFuncSetAttribute(k4, cudaFuncAttributeMaxDynamicSharedMemorySize, s4);

    k0<<<148, 512>>>(w2_1, wd_1, hw1, w2_0, w1_1, wd_0);
    k1<<<256, 512, s1>>>(x, w1_0, b1_0);
    k2<<<256, 512, s2>>>(x, b2_0, bd_0);
    k3<<<256, 512, s3>>>(b1_1);
    k4<<<256, 512, s4>>>(tl, b2_1, bd_1, hb1, hw2, hb2, out);
}

// round 11
// speedup vs baseline: 2.8121x; 1.0374x over previous
#include <cuda_runtime.h>
#include <cstddef>
#include <cstdint>

typedef unsigned long long ull;

// ---------------- gmem scratch ----------------
__device__ float g_h1 [100 * 21 * 4096];
__device__ float g_y  [100 *  9 * 4096];
__device__ float g_h11[200 *  5 * 4096];
// transposed weights (filled by k0 each launch)
__device__ float g_w2T [1000 * 200];    // w2_1: [cik][co]
__device__ float g_wdT [100 * 200];     // wd_1: [ci][co]
__device__ float g_hw1T[8 * 200 * 100]; // hw1:  [task][c2][c1]
__device__ float g_w20T[500 * 100];     // w2_0: [cik][co]
__device__ float g_w11T[500 * 200];     // w1_1: [cik][co]
__device__ float g_wd0T[30 * 100];      // wd_0: [ci][co]
__device__ float g_w10T[150 * 100];     // w1_0: [cik][co]

// ---------------- helpers ----------------
__device__ __forceinline__ void cp16(float* dst_smem, const float* src) {
    uint32_t s = (uint32_t)__cvta_generic_to_shared(dst_smem);
    asm volatile("cp.async.cg.shared.global [%0], [%1], 16;\n" :: "r"(s), "l"(src));
}
__device__ __forceinline__ void cp_commit() { asm volatile("cp.async.commit_group;\n"); }
__device__ __forceinline__ void cp_wait0()  { asm volatile("cp.async.wait_group 0;\n"); }

__device__ __forceinline__ ull pack2(float x, float y) {
    ull r; asm("mov.b64 %0, {%1, %2};" : "=l"(r) : "f"(x), "f"(y)); return r;
}
__device__ __forceinline__ ull bcast2(float x) { return pack2(x, x); }
__device__ __forceinline__ float2 unpack2(ull v) {
    float2 f; asm("mov.b64 {%0, %1}, %2;" : "=f"(f.x), "=f"(f.y) : "l"(v)); return f;
}
__device__ __forceinline__ void fma2(ull& d, ull a, ull b) {
    asm("fma.rn.f32x2 %0, %1, %2, %3;" : "=l"(d) : "l"(a), "l"(b), "l"(d));
}
__device__ __forceinline__ void fma4(float4& a, float w, const float4& v) {
    a.x = fmaf(w, v.x, a.x); a.y = fmaf(w, v.y, a.y);
    a.z = fmaf(w, v.z, a.z); a.w = fmaf(w, v.w, a.w);
}

// =====================================================================================
// K0: weight transposes
// =====================================================================================
__global__ __launch_bounds__(512, 2) void k0(
    const float* __restrict__ w2_1, const float* __restrict__ wd_1,
    const float* __restrict__ hw1,  const float* __restrict__ w2_0,
    const float* __restrict__ w1_1, const float* __restrict__ wd_0,
    const float* __restrict__ w1_0)
{
    const int i = blockIdx.x * blockDim.x + threadIdx.x;
    const int n = blockDim.x * gridDim.x;
    for (int j = i; j < 200000; j += n) {
        int cik = j / 200, co = j - cik * 200;
        g_w2T[j] = __ldg(w2_1 + co * 1000 + cik);
    }
    for (int j = i; j < 20000; j += n) {
        int ci = j / 200, co = j - ci * 200;
        g_wdT[j] = __ldg(wd_1 + co * 100 + ci);
    }
    for (int j = i; j < 160000; j += n) {
        int t = j / 20000; int r = j - t * 20000; int c2 = r / 100; int c1 = r - c2 * 100;
        g_hw1T[j] = __ldg(hw1 + ((size_t)t * 100 + c1) * 200 + c2);
    }
    for (int j = i; j < 50000; j += n) {
        int cik = j / 100, co = j - cik * 100;
        g_w20T[j] = __ldg(w2_0 + co * 500 + cik);
    }
    for (int j = i; j < 100000; j += n) {
        int cik = j / 200, co = j - cik * 200;
        g_w11T[j] = __ldg(w1_1 + co * 500 + cik);
    }
    for (int j = i; j < 3000; j += n) {
        int ci = j / 100, co = j - ci * 100;
        g_wd0T[j] = __ldg(wd_0 + co * 30 + ci);
    }
    for (int j = i; j < 15000; j += n) {
        int cik = j / 100, co = j - cik * 100;
        g_w10T[j] = __ldg(w1_0 + co * 150 + cik);
    }
}

// =====================================================================================
// K1: h1[co][t][b] = relu(conv1_0(x)) at t_glob = 235..255 (t=0..20)
// f32x2, co-pair x batch-pair, t in 3 phases of 7, direct transposed weight streaming.
// smem 48KB -> 2 CTAs/SM -> single wave.
// =====================================================================================
#define K1_X 12000                  // xs [(ci*25+tau)*16 + bl]
__global__ __launch_bounds__(512, 2) void k1(
    const float* __restrict__ x, const float* __restrict__ b1_0)
{
    extern __shared__ float sm[];
    const int tid = threadIdx.x;
    const int b0  = blockIdx.x * 16;

    for (int i = tid; i < K1_X; i += 512) {
        int ci = i / 400; int r = i - ci * 400; int bl = r / 25; int tau = r - bl * 25;
        sm[(ci * 25 + tau) * 16 + bl] = x[(size_t)(b0 + bl) * 7680 + ci * 256 + 231 + tau];
    }
    __syncthreads();

    const int cop = tid >> 3;          // 0..63, active < 50
    const int bgp = tid & 7;
    if (cop < 50) {
        const int co0 = 2 * cop, co1 = co0 + 1;
        const float bi0 = __ldg(b1_0 + co0), bi1 = __ldg(b1_0 + co1);
        #pragma unroll 1
        for (int ph = 0; ph < 3; ph++) {
            const int t0 = ph * 7;
            ull a0[7], a1[7];
            {
                ull p0 = bcast2(bi0), p1 = bcast2(bi1);
                #pragma unroll
                for (int tt = 0; tt < 7; tt++) { a0[tt] = p0; a1[tt] = p1; }
            }
            for (int ci = 0; ci < 30; ci++) {
                const float* xp = &sm[(ci * 25 + t0) * 16 + bgp * 2];
                ull v[11];
                #pragma unroll
                for (int u = 0; u < 11; u++) v[u] = *(const ull*)&xp[u * 16];
                #pragma unroll
                for (int k = 0; k < 5; k++) {
                    float2 w = *(const float2*)&g_w10T[(ci * 5 + k) * 100 + co0];
                    ull wx = bcast2(w.x), wy = bcast2(w.y);
                    #pragma unroll
                    for (int tt = 0; tt < 7; tt++) {
                        fma2(a0[tt], wx, v[tt + k]);
                        fma2(a1[tt], wy, v[tt + k]);
                    }
                }
            }
            #pragma unroll
            for (int tt = 0; tt < 7; tt++) {
                float2 f0 = unpack2(a0[tt]);
                float2 f1 = unpack2(a1[tt]);
                f0.x = fmaxf(f0.x, 0.f); f0.y = fmaxf(f0.y, 0.f);
                f1.x = fmaxf(f1.x, 0.f); f1.y = fmaxf(f1.y, 0.f);
                *(float2*)&g_h1[((size_t)co0 * 21 + t0 + tt) * 4096 + b0 + bgp * 2] = f0;
                *(float2*)&g_h1[((size_t)co1 * 21 + t0 + tt) * 4096 + b0 + bgp * 2] = f1;
            }
        }
    }
}

// =====================================================================================
// K2: y = relu(relu(conv2_0(h1)) + bd0 + wd0*x) at 9 pts.  f32x2 packed.  [R10 form]
// =====================================================================================
#define K2_H  33600                 // h1 tile [ci][t][16b]
#define K2_X  4320                  // xs2 [(ci*9+j)*16 + bl]
__global__ __launch_bounds__(512, 1) void k2(
    const float* __restrict__ x,
    const float* __restrict__ b2_0, const float* __restrict__ bd_0)
{
    extern __shared__ float sm[];
    float* h1s = sm;
    float* xs2 = sm + K2_H;
    const int tid = threadIdx.x;
    const int b0  = blockIdx.x * 16;

    for (int i = tid; i < 8400; i += 512) {
        int cit = i >> 2, q = i & 3;
        cp16(&h1s[cit * 16 + 4 * q], &g_h1[(size_t)cit * 4096 + b0 + 4 * q]);
    }
    cp_commit();

    for (int i = tid; i < K2_X; i += 512) {
        int ci = i / 144; int r = i - ci * 144; int j = r >> 4; int bl = r & 15;
        xs2[(ci * 9 + j) * 16 + bl] = x[(size_t)(b0 + bl) * 7680 + ci * 256 + 239 + 2 * j];
    }

    cp_wait0();
    __syncthreads();

    const int cop = tid >> 3;          // 0..63, active < 50
    const int bgp = tid & 7;
    if (cop < 50) {
        const int co0 = 2 * cop, co1 = co0 + 1;
        ull a[2][9];
        {
            ull b0v = bcast2(__ldg(b2_0 + co0));
            ull b1v = bcast2(__ldg(b2_0 + co1));
            #pragma unroll
            for (int j = 0; j < 9; j++) { a[0][j] = b0v; a[1][j] = b1v; }
        }
        for (int ci = 0; ci < 100; ci++) {
            const float* hp = &h1s[(ci * 21) * 16 + bgp * 2];
            ull v[21];
            #pragma unroll
            for (int t = 0; t < 21; t++) v[t] = *(const ull*)&hp[t * 16];
            #pragma unroll
            for (int k = 0; k < 5; k++) {
                float2 w = *(const float2*)&g_w20T[(ci * 5 + k) * 100 + co0];
                ull wx = bcast2(w.x), wy = bcast2(w.y);
                #pragma unroll
                for (int j = 0; j < 9; j++) {
                    fma2(a[0][j], wx, v[2 * j + k]);
                    fma2(a[1][j], wy, v[2 * j + k]);
                }
            }
        }
        {
            float bd0v = __ldg(bd_0 + co0), bd1v = __ldg(bd_0 + co1);
            #pragma unroll
            for (int j = 0; j < 9; j++) {
                float2 f0 = unpack2(a[0][j]);
                float2 f1 = unpack2(a[1][j]);
                a[0][j] = pack2(fmaxf(f0.x, 0.f) + bd0v, fmaxf(f0.y, 0.f) + bd0v);
                a[1][j] = pack2(fmaxf(f1.x, 0.f) + bd1v, fmaxf(f1.y, 0.f) + bd1v);
            }
        }
        for (int ci = 0; ci < 30; ci++) {
            float2 w = *(const float2*)&g_wd0T[ci * 100 + co0];
            ull wx = bcast2(w.x), wy = bcast2(w.y);
            const float* xp = &xs2[(ci * 9) * 16 + bgp * 2];
            #pragma unroll
            for (int j = 0; j < 9; j++) {
                ull xv = *(const ull*)&xp[j * 16];
                fma2(a[0][j], wx, xv);
                fma2(a[1][j], wy, xv);
            }
        }
        #pragma unroll
        for (int j = 0; j < 9; j++) {
            float2 f0 = unpack2(a[0][j]);
            float2 f1 = unpack2(a[1][j]);
            f0.x = fmaxf(f0.x, 0.f); f0.y = fmaxf(f0.y, 0.f);
            f1.x = fmaxf(f1.x, 0.f); f1.y = fmaxf(f1.y, 0.f);
            *(float2*)&g_y[((size_t)co0 * 9 + j) * 4096 + b0 + bgp * 2] = f0;
            *(float2*)&g_y[((size_t)co1 * 9 + j) * 4096 + b0 + bgp * 2] = f1;
        }
    }
}

// =====================================================================================
// K3: h11 = relu(conv1_1(y, dil=2)) at 5 pts.  [reverted to R9 scalar/float4 form]
// =====================================================================================
#define K3_Y  14400                 // y tile [ci][j][16b]
__global__ __launch_bounds__(512, 2) void k3(const float* __restrict__ b1_1)
{
    extern __shared__ float sm[];
    float* ys = sm;
    const int tid = threadIdx.x;
    const int b0  = blockIdx.x * 16;

    for (int i = tid; i < 3600; i += 512) {
        int cij = i >> 2, q = i & 3;
        cp16(&ys[cij * 16 + 4 * q], &g_y[(size_t)cij * 4096 + b0 + 4 * q]);
    }
    cp_commit();
    cp_wait0();
    __syncthreads();

    const int cog = tid >> 2;          // 0..127, active < 100 (co pairs)
    const int bg  = tid & 3;
    if (cog < 100) {
        const int co0 = 2 * cog, co1 = co0 + 1;
        float4 a0[5], a1[5];
        {
            float bi0 = __ldg(b1_1 + co0), bi1 = __ldg(b1_1 + co1);
            #pragma unroll
            for (int i = 0; i < 5; i++) {
                a0[i] = make_float4(bi0, bi0, bi0, bi0);
                a1[i] = make_float4(bi1, bi1, bi1, bi1);
            }
        }
        for (int ci = 0; ci < 100; ci++) {
            const float* yp = &ys[(ci * 9) * 16 + bg * 4];
            #pragma unroll
            for (int k = 0; k < 5; k++) {
                float2 w = *(const float2*)&g_w11T[(ci * 5 + k) * 200 + co0];
                #pragma unroll
                for (int i = 0; i < 5; i++) {
                    float4 av = *(const float4*)&yp[(k + i) * 16];
                    fma4(a0[i], w.x, av);
                    fma4(a1[i], w.y, av);
                }
            }
        }
        #pragma unroll
        for (int i = 0; i < 5; i++) {
            float4 r0, r1;
            r0.x = fmaxf(a0[i].x, 0.f); r0.y = fmaxf(a0[i].y, 0.f);
            r0.z = fmaxf(a0[i].z, 0.f); r0.w = fmaxf(a0[i].w, 0.f);
            r1.x = fmaxf(a1[i].x, 0.f); r1.y = fmaxf(a1[i].y, 0.f);
            r1.z = fmaxf(a1[i].z, 0.f); r1.w = fmaxf(a1[i].w, 0.f);
            *(float4*)&g_h11[((size_t)co0 * 5 + i) * 4096 + b0 + bg * 4] = r0;
            *(float4*)&g_h11[((size_t)co1 * 5 + i) * 4096 + b0 + bg * 4] = r1;
        }
    }
}

// =====================================================================================
// K4: feat = relu(relu(conv2_1(h11)@t=255) + bd1 + wd1*y[t=255]); fused head. [R10 form]
// =====================================================================================
#define K4_H    16000
#define K4_YR   1600
#define K4_FT   3216
#define K4_HH   1664
__global__ __launch_bounds__(512, 2) void k4(
    const int* __restrict__ task_labels,
    const float* __restrict__ b2_1, const float* __restrict__ bd_1,
    const float* __restrict__ hb1,
    const float* __restrict__ hw2, const float* __restrict__ hb2,
    float* __restrict__ out)
{
    extern __shared__ float sm[];
    float* h11s = sm;
    float* yres = sm + K4_H;
    float* feat = sm + K4_H + K4_YR;
    float* smH  = sm + K4_H + K4_YR + K4_FT;
    const int tid = threadIdx.x;
    const int b0  = blockIdx.x * 16;

    const int cog = tid >> 2;          // 0..127, active < 100
    const int bg  = tid & 3;
    const bool act = (cog < 100);
    const int co0 = 2 * cog, co1 = 2 * cog + 1;

    for (int i = tid; i < 4000; i += 512) {
        int cik = i >> 2, q = i & 3;
        cp16(&h11s[cik * 16 + 4 * q], &g_h11[(size_t)cik * 4096 + b0 + 4 * q]);
    }
    cp_commit();

    for (int i = tid; i < K4_YR; i += 512) {
        int blx = i & 15, ci = i >> 4;
        yres[ci * 16 + blx] = g_y[((size_t)ci * 9 + 8) * 4096 + b0 + blx];
    }

    cp_wait0();
    __syncthreads();

    if (act) {
        ull c0l = 0, c0h = 0, c1l = 0, c1h = 0;
        #pragma unroll 2
        for (int q = 0; q < 250; q++) {
            ulonglong2 av0 = *(const ulonglong2*)&h11s[(4 * q + 0) * 16 + bg * 4];
            ulonglong2 av1 = *(const ulonglong2*)&h11s[(4 * q + 1) * 16 + bg * 4];
            ulonglong2 av2 = *(const ulonglong2*)&h11s[(4 * q + 2) * 16 + bg * 4];
            ulonglong2 av3 = *(const ulonglong2*)&h11s[(4 * q + 3) * 16 + bg * 4];
            float2 w0 = *(const float2*)&g_w2T[(4 * q + 0) * 200 + co0];
            float2 w1 = *(const float2*)&g_w2T[(4 * q + 1) * 200 + co0];
            float2 w2 = *(const float2*)&g_w2T[(4 * q + 2) * 200 + co0];
            float2 w3 = *(const float2*)&g_w2T[(4 * q + 3) * 200 + co0];
            ull w0x = bcast2(w0.x), w0y = bcast2(w0.y);
            ull w1x = bcast2(w1.x), w1y = bcast2(w1.y);
            ull w2x = bcast2(w2.x), w2y = bcast2(w2.y);
            ull w3x = bcast2(w3.x), w3y = bcast2(w3.y);
            fma2(c0l, w0x, av0.x); fma2(c0h, w0x, av0.y);
            fma2(c1l, w0y, av0.x); fma2(c1h, w0y, av0.y);
            fma2(c0l, w1x, av1.x); fma2(c0h, w1x, av1.y);
            fma2(c1l, w1y, av1.x); fma2(c1h, w1y, av1.y);
            fma2(c0l, w2x, av2.x); fma2(c0h, w2x, av2.y);
            fma2(c1l, w2y, av2.x); fma2(c1h, w2y, av2.y);
            fma2(c0l, w3x, av3.x); fma2(c0h, w3x, av3.y);
            fma2(c1l, w3y, av3.x); fma2(c1h, w3y, av3.y);
        }

        ull r0l = 0, r0h = 0, r1l = 0, r1h = 0;
        #pragma unroll 5
        for (int q = 0; q < 25; q++) {
            ulonglong2 yv0 = *(const ulonglong2*)&yres[(4 * q + 0) * 16 + bg * 4];
            ulonglong2 yv1 = *(const ulonglong2*)&yres[(4 * q + 1) * 16 + bg * 4];
            ulonglong2 yv2 = *(const ulonglong2*)&yres[(4 * q + 2) * 16 + bg * 4];
            ulonglong2 yv3 = *(const ulonglong2*)&yres[(4 * q + 3) * 16 + bg * 4];
            float2 w0 = *(const float2*)&g_wdT[(4 * q + 0) * 200 + co0];
            float2 w1 = *(const float2*)&g_wdT[(4 * q + 1) * 200 + co0];
            float2 w2 = *(const float2*)&g_wdT[(4 * q + 2) * 200 + co0];
            float2 w3 = *(const float2*)&g_wdT[(4 * q + 3) * 200 + co0];
            ull w0x = bcast2(w0.x), w0y = bcast2(w0.y);
            ull w1x = bcast2(w1.x), w1y = bcast2(w1.y);
            ull w2x = bcast2(w2.x), w2y = bcast2(w2.y);
            ull w3x = bcast2(w3.x), w3y = bcast2(w3.y);
            fma2(r0l, w0x, yv0.x); fma2(r0h, w0x, yv0.y);
            fma2(r1l, w0y, yv0.x); fma2(r1h, w0y, yv0.y);
            fma2(r0l, w1x, yv1.x); fma2(r0h, w1x, yv1.y);
            fma2(r1l, w1y, yv1.x); fma2(r1h, w1y, yv1.y);
            fma2(r0l, w2x, yv2.x); fma2(r0h, w2x, yv2.y);
            fma2(r1l, w2y, yv2.x); fma2(r1h, w2y, yv2.y);
            fma2(r0l, w3x, yv3.x); fma2(r0h, w3x, yv3.y);
            fma2(r1l, w3y, yv3.x); fma2(r1h, w3y, yv3.y);
        }

        float b2v0 = __ldg(b2_1 + co0), bdv0 = __ldg(bd_1 + co0);
        float b2v1 = __ldg(b2_1 + co1), bdv1 = __ldg(bd_1 + co1);
        float2 cl0 = unpack2(c0l), ch0 = unpack2(c0h);
        float2 cl1 = unpack2(c1l), ch1 = unpack2(c1h);
        float2 sl0 = unpack2(r0l), sh0 = unpack2(r0h);
        float2 sl1 = unpack2(r1l), sh1 = unpack2(r1h);
        float conv0[4] = { cl0.x, cl0.y, ch0.x, ch0.y };
        float conv1[4] = { cl1.x, cl1.y, ch1.x, ch1.y };
        float res0[4]  = { sl0.x, sl0.y, sh0.x, sh0.y };
        float res1[4]  = { sl1.x, sl1.y, sh1.x, sh1.y };
        #pragma unroll
        for (int b = 0; b < 4; b++) {
            int blx = bg * 4 + b;
            feat[blx * 201 + co0] = fmaxf(fmaxf(conv0[b] + b2v0, 0.f) + bdv0 + res0[b], 0.f);
            feat[blx * 201 + co1] = fmaxf(fmaxf(conv1[b] + b2v1, 0.f) + bdv1 + res1[b], 0.f);
        }
    }
    __syncthreads();

    for (int o = tid; o < 800; o += 512) {
        int blx = o / 50, c1p = o - blx * 50;
        int task = __ldg(task_labels + b0 + blx);
        const float* Wt = g_hw1T + task * 20000 + c1p * 2;
        const float* fr = &feat[blx * 201];
        ull acc = 0;
        #pragma unroll 4
        for (int c2 = 0; c2 < 200; c2++) {
            float2 w = *(const float2*)&Wt[c2 * 100];
            ull wp; asm("mov.b64 %0, {%1, %2};" : "=l"(wp) : "f"(w.x), "f"(w.y));
            fma2(acc, bcast2(fr[c2]), wp);
        }
        float2 s = unpack2(acc);
        float2 hb = *(const float2*)&hb1[task * 100 + c1p * 2];
        smH[blx * 104 + c1p * 2 + 0] = tanhf(s.x + hb.x);
        smH[blx * 104 + c1p * 2 + 1] = tanhf(s.y + hb.y);
    }
    __syncthreads();

    if (tid < 16) {
        int blx = tid;
        int task = __ldg(task_labels + b0 + blx);
        const float4* W = (const float4*)(hw2 + task * 100);
        const float* hr = &smH[blx * 104];
        float a0 = 0.f, a1 = 0.f, a2 = 0.f, a3 = 0.f;
        #pragma unroll 5
        for (int q = 0; q < 25; q++) {
            float4 wv = __ldg(W + q);
            a0 = fmaf(hr[4 * q + 0], wv.x, a0);
            a1 = fmaf(hr[4 * q + 1], wv.y, a1);
            a2 = fmaf(hr[4 * q + 2], wv.z, a2);
            a3 = fmaf(hr[4 * q + 3], wv.w, a3);
        }
        out[b0 + blx] = (a0 + a1) + (a2 + a3) + __ldg(hb2 + task);
    }
}

// =====================================================================================
extern "C" void kernel_launch(void* const* d_in, const int* in_sizes, int n_in,
                              void* d_out, int out_size)
{
    const float* x    = (const float*)d_in[0];
    const int*   tl   = (const int*)  d_in[1];
    const float* w1_0 = (const float*)d_in[2];
    const float* b1_0 = (const float*)d_in[3];
    const float* w2_0 = (const float*)d_in[4];
    const float* b2_0 = (const float*)d_in[5];
    const float* wd_0 = (const float*)d_in[6];
    const float* bd_0 = (const float*)d_in[7];
    const float* w1_1 = (const float*)d_in[8];
    const float* b1_1 = (const float*)d_in[9];
    const float* w2_1 = (const float*)d_in[10];
    const float* b2_1 = (const float*)d_in[11];
    const float* wd_1 = (const float*)d_in[12];
    const float* bd_1 = (const float*)d_in[13];
    const float* hw1  = (const float*)d_in[14];
    const float* hb1  = (const float*)d_in[15];
    const float* hw2  = (const float*)d_in[16];
    const float* hb2  = (const float*)d_in[17];
    float* out = (float*)d_out;

    const int s1 = K1_X * 4;                              // 48,000 B
    const int s2 = (K2_H + K2_X) * 4;
    const int s3 = K3_Y * 4;
    const int s4 = (K4_H + K4_YR + K4_FT + K4_HH) * 4;
    cudaFuncSetAttribute(k1, cudaFuncAttributeMaxDynamicSharedMemorySize, s1);
    cudaFuncSetAttribute(k2, cudaFuncAttributeMaxDynamicSharedMemorySize, s2);
    cudaFuncSetAttribute(k3, cudaFuncAttributeMaxDynamicSharedMemorySize, s3);
    cudaFuncSetAttribute(k4, cudaFuncAttributeMaxDynamicSharedMemorySize, s4);

    k0<<<148, 512>>>(w2_1, wd_1, hw1, w2_0, w1_1, wd_0, w1_0);
    k1<<<256, 512, s1>>>(x, b1_0);
    k2<<<256, 512, s2>>>(x, b2_0, bd_0);
    k3<<<256, 512, s3>>>(b1_1);
    k4<<<256, 512, s4>>>(tl, b2_1, bd_1, hb1, hw2, hb2, out);
}